// round 5
// baseline (speedup 1.0000x reference)
#include <cuda_runtime.h>
#include <cuda_bf16.h>
#include <cstdint>
#include <math.h>

// Problem constants
#define BATCH 4
#define SEQ   2048
#define DM    2048
#define NH    16
#define DH    128
#define RH    64
#define NTOK  (BATCH*SEQ)      // 8192
#define QKVN  (3*DM)           // 6144
#define BH    (BATCH*NH)       // 64

// ---------------- scratch (device globals) ----------------------------------
__device__ float g_qkv[(size_t)NTOK * QKVN];

__device__ __nv_bfloat16 g_xhi[(size_t)NTOK*DM];
__device__ __nv_bfloat16 g_xlo[(size_t)NTOK*DM];
__device__ __nv_bfloat16 g_ahi[(size_t)NTOK*DM];
__device__ __nv_bfloat16 g_alo[(size_t)NTOK*DM];
__device__ __nv_bfloat16 g_wqkvT_hi[(size_t)QKVN*DM];
__device__ __nv_bfloat16 g_wqkvT_lo[(size_t)QKVN*DM];
__device__ __nv_bfloat16 g_woutT_hi[(size_t)DM*DM];
__device__ __nv_bfloat16 g_woutT_lo[(size_t)DM*DM];

// attention operands, bf16 hi/lo
__device__ __nv_bfloat16 g_qhi[(size_t)BH*SEQ*DH];
__device__ __nv_bfloat16 g_qlo[(size_t)BH*SEQ*DH];
__device__ __nv_bfloat16 g_khi[(size_t)BH*SEQ*DH];
__device__ __nv_bfloat16 g_klo[(size_t)BH*SEQ*DH];
__device__ __nv_bfloat16 g_vthi[(size_t)BH*DH*SEQ];   // [bh, d, s]
__device__ __nv_bfloat16 g_vtlo[(size_t)BH*DH*SEQ];

// ---------------- PTX helpers -------------------------------------------------
__device__ __forceinline__ uint32_t smem_u32(const void* p) {
    uint32_t a;
    asm("{ .reg .u64 t; cvta.to.shared.u64 t, %1; cvt.u32.u64 %0, t; }" : "=r"(a) : "l"(p));
    return a;
}
#define CP_ASYNC16(dst, src) \
    asm volatile("cp.async.cg.shared.global [%0], [%1], 16;" :: "r"(dst), "l"(src))
#define CP_COMMIT() asm volatile("cp.async.commit_group;" ::: "memory")
#define CP_WAIT(n)  asm volatile("cp.async.wait_group %0;" :: "n"(n) : "memory")

__device__ __forceinline__ void ldsm_x4(uint32_t* r, uint32_t addr) {
    asm volatile("ldmatrix.sync.aligned.m8n8.x4.shared.b16 {%0,%1,%2,%3}, [%4];"
        : "=r"(r[0]), "=r"(r[1]), "=r"(r[2]), "=r"(r[3]) : "r"(addr));
}
__device__ __forceinline__ void mma_bf16(float* d, const uint32_t* a,
                                         uint32_t b0, uint32_t b1) {
    asm volatile("mma.sync.aligned.m16n8k16.row.col.f32.bf16.bf16.f32 "
        "{%0,%1,%2,%3}, {%4,%5,%6,%7}, {%8,%9}, {%0,%1,%2,%3};"
        : "+f"(d[0]), "+f"(d[1]), "+f"(d[2]), "+f"(d[3])
        : "r"(a[0]), "r"(a[1]), "r"(a[2]), "r"(a[3]), "r"(b0), "r"(b1));
}
__device__ __forceinline__ void pack_hilo(float x, float y, uint32_t& hi, uint32_t& lo) {
    __nv_bfloat162 h = __floats2bfloat162_rn(x, y);
    float rx = x - __bfloat162float(h.x);
    float ry = y - __bfloat162float(h.y);
    __nv_bfloat162 l = __floats2bfloat162_rn(rx, ry);
    hi = *reinterpret_cast<uint32_t*>(&h);
    lo = *reinterpret_cast<uint32_t*>(&l);
}

// ---------------- split / transpose-split kernels ----------------------------
__global__ void split_a(const float* __restrict__ in,
                        __nv_bfloat16* __restrict__ hi,
                        __nv_bfloat16* __restrict__ lo, int n4)
{
    int i = blockIdx.x * blockDim.x + threadIdx.x;
    if (i >= n4) return;
    float4 v = ((const float4*)in)[i];
    uint32_t h0, l0, h1, l1;
    pack_hilo(v.x, v.y, h0, l0);
    pack_hilo(v.z, v.w, h1, l1);
    ((uint32_t*)hi)[i*2]   = h0;  ((uint32_t*)hi)[i*2+1] = h1;
    ((uint32_t*)lo)[i*2]   = l0;  ((uint32_t*)lo)[i*2+1] = l1;
}

// W[R,C] fp32 -> T[C,R] bf16 hi/lo
__global__ void transpose_split(const float* __restrict__ W,
                                __nv_bfloat16* __restrict__ Thi,
                                __nv_bfloat16* __restrict__ Tlo, int R, int C)
{
    __shared__ float t[32][33];
    int c0 = blockIdx.x * 32, r0 = blockIdx.y * 32;
    int tx = threadIdx.x, ty = threadIdx.y;
#pragma unroll
    for (int j = 0; j < 4; j++)
        t[ty + j*8][tx] = W[(size_t)(r0 + ty + j*8) * C + c0 + tx];
    __syncthreads();
#pragma unroll
    for (int j = 0; j < 4; j++) {
        int cc = c0 + ty + j*8;
        float v = t[tx][ty + j*8];
        __nv_bfloat16 h = __float2bfloat16(v);
        __nv_bfloat16 l = __float2bfloat16(v - __bfloat162float(h));
        Thi[(size_t)cc * R + r0 + tx] = h;
        Tlo[(size_t)cc * R + r0 + tx] = l;
    }
}

// V slice of g_qkv -> [bh, d, s] bf16 hi/lo
__global__ void v_transpose(const float* __restrict__ qkv)
{
    __shared__ float t[32][33];
    const int b = blockIdx.z >> 4, h = blockIdx.z & 15;
    const int d0 = blockIdx.x * 32, s0 = blockIdx.y * 32;
    const int tx = threadIdx.x, ty = threadIdx.y;
#pragma unroll
    for (int j = 0; j < 4; j++)
        t[ty + j*8][tx] = qkv[(size_t)(b * SEQ + s0 + ty + j*8) * QKVN
                              + 2*DM + h*DH + d0 + tx];
    __syncthreads();
#pragma unroll
    for (int j = 0; j < 4; j++) {
        int dd = d0 + ty + j*8;
        float v = t[tx][ty + j*8];                     // V[s0+tx][dd]
        __nv_bfloat16 hh = __float2bfloat16(v);
        __nv_bfloat16 ll = __float2bfloat16(v - __bfloat162float(hh));
        size_t o = ((size_t)blockIdx.z * DH + dd) * SEQ + s0 + tx;
        g_vthi[o] = hh;
        g_vtlo[o] = ll;
    }
}

// ---------------- RoPE -> bf16 hi/lo Q,K [bh,s,d] ----------------------------
__global__ void rope_split(const float* __restrict__ qkv,
                           const float* __restrict__ rc,
                           const float* __restrict__ rs)
{
    const int idx = blockIdx.x * blockDim.x + threadIdx.x;
    const int j = idx & (RH - 1);
    const int s = (idx >> 6) & (SEQ - 1);
    const int h = (idx >> 17) & (NH - 1);
    const int b = idx >> 21;

    const float* row = qkv + (size_t)(b * SEQ + s) * QKVN;
    const float c  = rc[s * RH + j];
    const float sn = rs[s * RH + j];
    const int col = h * DH + 2 * j;

    const float qe = row[col],      qo = row[col + 1];
    const float ke = row[DM + col], ko = row[DM + col + 1];

    const float q0 = qe * c - qo * sn, q1 = qe * sn + qo * c;
    const float k0 = ke * c - ko * sn, k1 = ke * sn + ko * c;

    const size_t o2 = (((size_t)((b * NH + h) * SEQ + s)) * DH + 2 * j) >> 1;
    uint32_t hi, lo;
    pack_hilo(q0, q1, hi, lo);
    ((uint32_t*)g_qhi)[o2] = hi; ((uint32_t*)g_qlo)[o2] = lo;
    pack_hilo(k0, k1, hi, lo);
    ((uint32_t*)g_khi)[o2] = hi; ((uint32_t*)g_klo)[o2] = lo;
}

// ---------------- bf16x3 GEMM via mma.sync -----------------------------------
// C[M,N] = A[M,K] @ B^T (B stored [N,K] K-major) + bias.
// CTA tile 256x128, 512 threads (16 warps, 4x4), warp tile 64x32, K-chunk 32,
// double-buffered cp.async.  1 CTA/SM, 48 KB feed per stage for 2x MMA work.
#define TK 32
#define STR 80                 // smem row stride in bytes (32 bf16 + 8 pad)
#define ATILE (256*STR)        // 20480
#define BTILE (128*STR)        // 10240
#define STAGE (2*ATILE + 2*BTILE)   // 61440
#define GEMM_SMEM (2*STAGE)    // 122880

__device__ __forceinline__ void gemm_load_stage(
    uint32_t st, const __nv_bfloat16* Ahi, const __nv_bfloat16* Alo,
    const __nv_bfloat16* Bhi, const __nv_bfloat16* Blo,
    int bm, int bn, int kt, int K, int tid)
{
#pragma unroll
    for (int it = 0; it < 6; it++) {
        int idx = it * 512 + tid;
        if (idx < 2048) {
            int t = idx >> 10, rem = idx & 1023, r = rem >> 2, c = rem & 3;
            uint32_t dst = st + t * ATILE + r * STR + c * 16;
            const void* src = (t ? Alo : Ahi) + (size_t)(bm + r) * K + kt + c * 8;
            CP_ASYNC16(dst, src);
        } else {
            int j = idx - 2048;
            int t = j >> 9, rem = j & 511, r = rem >> 2, c = rem & 3;
            uint32_t dst = st + 2 * ATILE + t * BTILE + r * STR + c * 16;
            const void* src = (t ? Blo : Bhi) + (size_t)(bn + r) * K + kt + c * 8;
            CP_ASYNC16(dst, src);
        }
    }
}

__global__ __launch_bounds__(512)
void gemm_tc(const __nv_bfloat16* __restrict__ Ahi, const __nv_bfloat16* __restrict__ Alo,
             const __nv_bfloat16* __restrict__ Bhi, const __nv_bfloat16* __restrict__ Blo,
             const float* __restrict__ bias, float* __restrict__ C,
             int M, int N, int K)
{
    extern __shared__ char sm[];
    const uint32_t sbase = smem_u32(sm);

    const int tid = threadIdx.x;
    const int wid = tid >> 5;
    const int lane = tid & 31;
    const int warpM = wid >> 2;       // 0..3 (64 rows each)
    const int warpN = wid & 3;        // 0..3 (32 cols each)
    const int bn = blockIdx.x * 128;
    const int bm = blockIdx.y * 256;

    float acc[4][4][4];
#pragma unroll
    for (int mi = 0; mi < 4; mi++)
#pragma unroll
        for (int ni = 0; ni < 4; ni++)
#pragma unroll
            for (int r = 0; r < 4; r++) acc[mi][ni][r] = 0.f;

    const int NI = K / TK;

    gemm_load_stage(sbase, Ahi, Alo, Bhi, Blo, bm, bn, 0, K, tid);
    CP_COMMIT();

    for (int i = 0; i < NI; i++) {
        if (i + 1 < NI) {
            gemm_load_stage(sbase + ((i + 1) & 1) * STAGE, Ahi, Alo, Bhi, Blo,
                            bm, bn, (i + 1) * TK, K, tid);
            CP_COMMIT();
            CP_WAIT(1);
        } else {
            CP_WAIT(0);
        }
        __syncthreads();

        const uint32_t st = sbase + (i & 1) * STAGE;
        const uint32_t Ah = st, Al = st + ATILE;
        const uint32_t Bh = st + 2 * ATILE, Bl = st + 2 * ATILE + BTILE;

#pragma unroll
        for (int ks = 0; ks < 2; ks++) {
            const uint32_t ko = ks * 32 + (lane >> 4) * 16;
            const uint32_t arow = (warpM * 64 + (lane & 15)) * STR + ko;
            const uint32_t brow = (warpN * 32 + (lane & 15)) * STR + ko;

            uint32_t ahf[4][4], alf[4][4], bhf[2][4], blf[2][4];
#pragma unroll
            for (int mi = 0; mi < 4; mi++) {
                ldsm_x4(ahf[mi], Ah + arow + mi * 16 * STR);
                ldsm_x4(alf[mi], Al + arow + mi * 16 * STR);
            }
#pragma unroll
            for (int pi = 0; pi < 2; pi++) {
                ldsm_x4(bhf[pi], Bh + brow + pi * 16 * STR);
                ldsm_x4(blf[pi], Bl + brow + pi * 16 * STR);
            }
#pragma unroll
            for (int mi = 0; mi < 4; mi++)
#pragma unroll
                for (int ni = 0; ni < 4; ni++) {
                    const int pi = ni >> 1, o = ni & 1;
                    mma_bf16(acc[mi][ni], ahf[mi], bhf[pi][o], bhf[pi][o + 2]);
                    mma_bf16(acc[mi][ni], ahf[mi], blf[pi][o], blf[pi][o + 2]);
                    mma_bf16(acc[mi][ni], alf[mi], bhf[pi][o], bhf[pi][o + 2]);
                }
        }
        __syncthreads();
    }

#pragma unroll
    for (int mi = 0; mi < 4; mi++) {
        const int r0 = bm + warpM * 64 + mi * 16 + (lane >> 2);
#pragma unroll
        for (int ni = 0; ni < 4; ni++) {
            const int c0 = bn + warpN * 32 + ni * 8 + (lane & 3) * 2;
            const float b0 = bias[c0], b1 = bias[c0 + 1];
            float2 v0 = make_float2(acc[mi][ni][0] + b0, acc[mi][ni][1] + b1);
            float2 v1 = make_float2(acc[mi][ni][2] + b0, acc[mi][ni][3] + b1);
            *(float2*)(C + (size_t)r0 * N + c0) = v0;
            *(float2*)(C + (size_t)(r0 + 8) * N + c0) = v1;
        }
    }
}

// ---------------- HMMA flash attention (unchanged from R4) -------------------
#define KSTR 272
#define VSTR 144
#define KTILE (64*KSTR)
#define VTILE (128*VSTR)
#define ASTAGE (2*KTILE + 2*VTILE)
#define QSTR 272
#define QTILE (128*QSTR)
#define ATTN_SMEM (2*QTILE + 2*ASTAGE)  // 212992

__device__ __forceinline__ void attn_load_kv(uint32_t st, int bh, int k0, int tid)
{
    const __nv_bfloat16* kh = g_khi;
    const __nv_bfloat16* kl = g_klo;
    const __nv_bfloat16* vh = g_vthi;
    const __nv_bfloat16* vl = g_vtlo;
#pragma unroll
    for (int it = 0; it < 16; it++) {
        int idx = it * 256 + tid;
        int sec = idx >> 10, rem = idx & 1023;
        if (sec < 2) {
            int r = rem >> 4, c = rem & 15;
            uint32_t dst = st + sec * KTILE + r * KSTR + c * 16;
            const void* src = (sec ? kl : kh) + ((size_t)bh * SEQ + k0 + r) * DH + c * 8;
            CP_ASYNC16(dst, src);
        } else {
            int r = rem >> 3, c = rem & 7;
            uint32_t dst = st + 2 * KTILE + (sec - 2) * VTILE + r * VSTR + c * 16;
            const void* src = (sec == 2 ? vh : vl) + ((size_t)bh * DH + r) * SEQ + k0 + c * 8;
            CP_ASYNC16(dst, src);
        }
    }
}

__global__ __launch_bounds__(256, 1)
void attn_hmma()
{
    extern __shared__ char sm[];
    const uint32_t sbase = smem_u32(sm);
    const uint32_t qb_smem = sbase;
    const uint32_t stage0 = sbase + 2 * QTILE;

    const int qb = 15 - blockIdx.x;
    const int h = blockIdx.y, b = blockIdx.z;
    const int bh = b * NH + h;
    const int q0 = qb * 128;
    const int tid = threadIdx.x;
    const int w = tid >> 5;
    const int lane = tid & 31;
    const float scale = 0.08838834764831845f;

#pragma unroll
    for (int it = 0; it < 16; it++) {
        int idx = it * 256 + tid;
        int sec = idx >> 11, rem = idx & 2047;
        int r = rem >> 4, c = rem & 15;
        uint32_t dst = qb_smem + sec * QTILE + r * QSTR + c * 16;
        const void* src = (sec ? g_qlo : g_qhi) + ((size_t)bh * SEQ + q0 + r) * DH + c * 8;
        CP_ASYNC16(dst, src);
    }
    CP_COMMIT();
    CP_WAIT(0);
    __syncthreads();

    uint32_t qh[8][4], ql[8][4];
    {
        const uint32_t arow = (w * 16 + (lane & 15)) * QSTR + (lane >> 4) * 16;
#pragma unroll
        for (int kt = 0; kt < 8; kt++) {
            ldsm_x4(qh[kt], qb_smem + arow + kt * 32);
            ldsm_x4(ql[kt], qb_smem + QTILE + arow + kt * 32);
        }
    }

    float oa[16][4];
#pragma unroll
    for (int dt = 0; dt < 16; dt++)
#pragma unroll
        for (int r = 0; r < 4; r++) oa[dt][r] = 0.f;
    float m0 = -1e30f, m1 = -1e30f, l0 = 0.f, l1 = 0.f;

    const int nch = 2 * qb + 2;

    attn_load_kv(stage0, bh, 0, tid);
    CP_COMMIT();

    for (int kb = 0; kb < nch; kb++) {
        if (kb + 1 < nch) {
            attn_load_kv(stage0 + ((kb + 1) & 1) * ASTAGE, bh, (kb + 1) * 64, tid);
            CP_COMMIT();
            CP_WAIT(1);
        } else {
            CP_WAIT(0);
        }
        __syncthreads();

        const uint32_t st = stage0 + (kb & 1) * ASTAGE;
        const int k0 = kb * 64;

        float e[8][4];
#pragma unroll
        for (int nt = 0; nt < 8; nt++)
#pragma unroll
            for (int r = 0; r < 4; r++) e[nt][r] = 0.f;

#pragma unroll
        for (int kt = 0; kt < 8; kt++) {
            const uint32_t ko = kt * 32 + (lane >> 4) * 16;
#pragma unroll
            for (int np = 0; np < 4; np++) {
                const uint32_t brow = (np * 16 + (lane & 15)) * KSTR + ko;
                uint32_t bhf[4], blf[4];
                ldsm_x4(bhf, st + brow);
                ldsm_x4(blf, st + KTILE + brow);
#pragma unroll
                for (int o = 0; o < 2; o++) {
                    const int nt = 2 * np + o;
                    mma_bf16(e[nt], qh[kt], bhf[o], bhf[o + 2]);
                    mma_bf16(e[nt], qh[kt], blf[o], blf[o + 2]);
                    mma_bf16(e[nt], ql[kt], bhf[o], bhf[o + 2]);
                }
            }
        }

#pragma unroll
        for (int nt = 0; nt < 8; nt++)
#pragma unroll
            for (int r = 0; r < 4; r++) e[nt][r] *= scale;

        const int row0 = q0 + w * 16 + (lane >> 2);
        if (kb >= 2 * qb) {
#pragma unroll
            for (int nt = 0; nt < 8; nt++) {
                const int col = k0 + nt * 8 + (lane & 3) * 2;
                if (col     > row0)     e[nt][0] = -1e30f;
                if (col + 1 > row0)     e[nt][1] = -1e30f;
                if (col     > row0 + 8) e[nt][2] = -1e30f;
                if (col + 1 > row0 + 8) e[nt][3] = -1e30f;
            }
        }

        float rm0 = e[0][0], rm1 = e[0][2];
#pragma unroll
        for (int nt = 0; nt < 8; nt++) {
            rm0 = fmaxf(rm0, fmaxf(e[nt][0], e[nt][1]));
            rm1 = fmaxf(rm1, fmaxf(e[nt][2], e[nt][3]));
        }
        rm0 = fmaxf(rm0, __shfl_xor_sync(0xffffffffu, rm0, 1));
        rm0 = fmaxf(rm0, __shfl_xor_sync(0xffffffffu, rm0, 2));
        rm1 = fmaxf(rm1, __shfl_xor_sync(0xffffffffu, rm1, 1));
        rm1 = fmaxf(rm1, __shfl_xor_sync(0xffffffffu, rm1, 2));

        const float mn0 = fmaxf(m0, rm0), mn1 = fmaxf(m1, rm1);
        const float al0 = __expf(m0 - mn0), al1 = __expf(m1 - mn1);
        m0 = mn0; m1 = mn1;

        float s0 = 0.f, s1 = 0.f;
#pragma unroll
        for (int nt = 0; nt < 8; nt++) {
            e[nt][0] = __expf(e[nt][0] - mn0);
            e[nt][1] = __expf(e[nt][1] - mn0);
            e[nt][2] = __expf(e[nt][2] - mn1);
            e[nt][3] = __expf(e[nt][3] - mn1);
            s0 += e[nt][0] + e[nt][1];
            s1 += e[nt][2] + e[nt][3];
        }
        s0 += __shfl_xor_sync(0xffffffffu, s0, 1);
        s0 += __shfl_xor_sync(0xffffffffu, s0, 2);
        s1 += __shfl_xor_sync(0xffffffffu, s1, 1);
        s1 += __shfl_xor_sync(0xffffffffu, s1, 2);
        l0 = l0 * al0 + s0;
        l1 = l1 * al1 + s1;

#pragma unroll
        for (int dt = 0; dt < 16; dt++) {
            oa[dt][0] *= al0; oa[dt][1] *= al0;
            oa[dt][2] *= al1; oa[dt][3] *= al1;
        }

        const uint32_t vb = st + 2 * KTILE;
#pragma unroll
        for (int kt2 = 0; kt2 < 4; kt2++) {
            const int ta = 2 * kt2, tb = ta + 1;
            uint32_t ph[4], pl[4];
            pack_hilo(e[ta][0], e[ta][1], ph[0], pl[0]);
            pack_hilo(e[ta][2], e[ta][3], ph[1], pl[1]);
            pack_hilo(e[tb][0], e[tb][1], ph[2], pl[2]);
            pack_hilo(e[tb][2], e[tb][3], ph[3], pl[3]);

            const uint32_t ko = kt2 * 32 + (lane >> 4) * 16;
#pragma unroll
            for (int np = 0; np < 8; np++) {
                const uint32_t brow = (np * 16 + (lane & 15)) * VSTR + ko;
                uint32_t bhf[4], blf[4];
                ldsm_x4(bhf, vb + brow);
                ldsm_x4(blf, vb + VTILE + brow);
#pragma unroll
                for (int o = 0; o < 2; o++) {
                    const int dt = 2 * np + o;
                    mma_bf16(oa[dt], ph, bhf[o], bhf[o + 2]);
                    mma_bf16(oa[dt], ph, blf[o], blf[o + 2]);
                    mma_bf16(oa[dt], pl, bhf[o], bhf[o + 2]);
                }
            }
        }
        __syncthreads();
    }

    const float inv0 = 1.f / l0, inv1 = 1.f / l1;
    const size_t tokA = (size_t)b * SEQ + q0 + w * 16 + (lane >> 2);
    const size_t tokB = tokA + 8;
    const int colb = h * DH + (lane & 3) * 2;
    uint32_t* ahi = (uint32_t*)g_ahi;
    uint32_t* alo = (uint32_t*)g_alo;
#pragma unroll
    for (int dt = 0; dt < 16; dt++) {
        const int col = colb + dt * 8;
        uint32_t hi, lo;
        pack_hilo(oa[dt][0] * inv0, oa[dt][1] * inv0, hi, lo);
        ahi[(tokA * DM + col) >> 1] = hi;
        alo[(tokA * DM + col) >> 1] = lo;
        pack_hilo(oa[dt][2] * inv1, oa[dt][3] * inv1, hi, lo);
        ahi[(tokB * DM + col) >> 1] = hi;
        alo[(tokB * DM + col) >> 1] = lo;
    }
}

// ---------------- launch -----------------------------------------------------
extern "C" void kernel_launch(void* const* d_in, const int* in_sizes, int n_in,
                              void* d_out, int out_size)
{
    const float* x     = (const float*)d_in[0];
    const float* w_qkv = (const float*)d_in[1];
    const float* b_qkv = (const float*)d_in[2];
    const float* w_out = (const float*)d_in[3];
    const float* b_out = (const float*)d_in[4];
    const float* rc    = (const float*)d_in[5];
    const float* rs    = (const float*)d_in[6];
    float* out = (float*)d_out;

    float* p_qkv;
    __nv_bfloat16 *p_xhi, *p_xlo, *p_ahi, *p_alo;
    __nv_bfloat16 *p_wqh, *p_wql, *p_woh, *p_wol;
    cudaGetSymbolAddress((void**)&p_qkv, g_qkv);
    cudaGetSymbolAddress((void**)&p_xhi, g_xhi);
    cudaGetSymbolAddress((void**)&p_xlo, g_xlo);
    cudaGetSymbolAddress((void**)&p_ahi, g_ahi);
    cudaGetSymbolAddress((void**)&p_alo, g_alo);
    cudaGetSymbolAddress((void**)&p_wqh, g_wqkvT_hi);
    cudaGetSymbolAddress((void**)&p_wql, g_wqkvT_lo);
    cudaGetSymbolAddress((void**)&p_woh, g_woutT_hi);
    cudaGetSymbolAddress((void**)&p_wol, g_woutT_lo);

    cudaFuncSetAttribute(gemm_tc,
                         cudaFuncAttributeMaxDynamicSharedMemorySize, GEMM_SMEM);
    cudaFuncSetAttribute(attn_hmma,
                         cudaFuncAttributeMaxDynamicSharedMemorySize, ATTN_SMEM);

    // 1) split x -> bf16 hi/lo
    {
        int n4 = NTOK * DM / 4;
        split_a<<<(n4 + 255) / 256, 256>>>(x, p_xhi, p_xlo, n4);
    }
    // 2) transpose+split weights
    transpose_split<<<dim3(QKVN / 32, DM / 32), dim3(32, 8)>>>(w_qkv, p_wqh, p_wql, DM, QKVN);
    transpose_split<<<dim3(DM / 32, DM / 32), dim3(32, 8)>>>(w_out, p_woh, p_wol, DM, DM);
    // 3) qkv = x @ w_qkv + b  (HMMA bf16x3, 256x128 tiles)
    gemm_tc<<<dim3(QKVN / 128, NTOK / 256), 512, GEMM_SMEM>>>(
        p_xhi, p_xlo, p_wqh, p_wql, b_qkv, p_qkv, NTOK, QKVN, DM);
    // 4) RoPE -> bf16 hi/lo Q,K ; V transpose -> [bh,d,s]
    rope_split<<<(BATCH * NH * SEQ * RH) / 256, 256>>>(p_qkv, rc, rs);
    v_transpose<<<dim3(DH / 32, SEQ / 32, BH), dim3(32, 8)>>>(p_qkv);
    // 5) HMMA flash attention -> g_ahi/g_alo
    attn_hmma<<<dim3(SEQ / 128, NH, BATCH), 256, ATTN_SMEM>>>();
    // 6) out = att @ w_out + b  (HMMA bf16x3, 256x128 tiles)
    gemm_tc<<<dim3(DM / 128, NTOK / 256), 512, GEMM_SMEM>>>(
        p_ahi, p_alo, p_woh, p_wol, b_out, out, NTOK, DM, DM);
}

// round 6
// speedup vs baseline: 1.2251x; 1.2251x over previous
#include <cuda_runtime.h>
#include <cuda_bf16.h>
#include <cstdint>
#include <math.h>

// Problem constants
#define BATCH 4
#define SEQ   2048
#define DM    2048
#define NH    16
#define DH    128
#define RH    64
#define NTOK  (BATCH*SEQ)      // 8192
#define QKVN  (3*DM)           // 6144
#define BH    (BATCH*NH)       // 64

// ---------------- scratch (device globals) ----------------------------------
__device__ float g_qkv[(size_t)NTOK * QKVN];

__device__ __nv_bfloat16 g_xhi[(size_t)NTOK*DM];
__device__ __nv_bfloat16 g_xlo[(size_t)NTOK*DM];
__device__ __nv_bfloat16 g_ahi[(size_t)NTOK*DM];
__device__ __nv_bfloat16 g_alo[(size_t)NTOK*DM];
__device__ __nv_bfloat16 g_wqkvT_hi[(size_t)QKVN*DM];
__device__ __nv_bfloat16 g_wqkvT_lo[(size_t)QKVN*DM];
__device__ __nv_bfloat16 g_woutT_hi[(size_t)DM*DM];
__device__ __nv_bfloat16 g_woutT_lo[(size_t)DM*DM];

// attention operands, bf16 hi/lo
__device__ __nv_bfloat16 g_qhi[(size_t)BH*SEQ*DH];
__device__ __nv_bfloat16 g_qlo[(size_t)BH*SEQ*DH];
__device__ __nv_bfloat16 g_khi[(size_t)BH*SEQ*DH];
__device__ __nv_bfloat16 g_klo[(size_t)BH*SEQ*DH];
__device__ __nv_bfloat16 g_vthi[(size_t)BH*DH*SEQ];   // [bh, d, s]
__device__ __nv_bfloat16 g_vtlo[(size_t)BH*DH*SEQ];

// ---------------- PTX helpers -------------------------------------------------
__device__ __forceinline__ uint32_t smem_u32(const void* p) {
    uint32_t a;
    asm("{ .reg .u64 t; cvta.to.shared.u64 t, %1; cvt.u32.u64 %0, t; }" : "=r"(a) : "l"(p));
    return a;
}
#define CP_ASYNC16(dst, src) \
    asm volatile("cp.async.cg.shared.global [%0], [%1], 16;" :: "r"(dst), "l"(src))
#define CP_COMMIT() asm volatile("cp.async.commit_group;" ::: "memory")
#define CP_WAIT(n)  asm volatile("cp.async.wait_group %0;" :: "n"(n) : "memory")

__device__ __forceinline__ void ldsm_x4(uint32_t* r, uint32_t addr) {
    asm volatile("ldmatrix.sync.aligned.m8n8.x4.shared.b16 {%0,%1,%2,%3}, [%4];"
        : "=r"(r[0]), "=r"(r[1]), "=r"(r[2]), "=r"(r[3]) : "r"(addr));
}
__device__ __forceinline__ void mma_bf16(float* d, const uint32_t* a,
                                         uint32_t b0, uint32_t b1) {
    asm volatile("mma.sync.aligned.m16n8k16.row.col.f32.bf16.bf16.f32 "
        "{%0,%1,%2,%3}, {%4,%5,%6,%7}, {%8,%9}, {%0,%1,%2,%3};"
        : "+f"(d[0]), "+f"(d[1]), "+f"(d[2]), "+f"(d[3])
        : "r"(a[0]), "r"(a[1]), "r"(a[2]), "r"(a[3]), "r"(b0), "r"(b1));
}
__device__ __forceinline__ void pack_hilo(float x, float y, uint32_t& hi, uint32_t& lo) {
    __nv_bfloat162 h = __floats2bfloat162_rn(x, y);
    float rx = x - __bfloat162float(h.x);
    float ry = y - __bfloat162float(h.y);
    __nv_bfloat162 l = __floats2bfloat162_rn(rx, ry);
    hi = *reinterpret_cast<uint32_t*>(&h);
    lo = *reinterpret_cast<uint32_t*>(&l);
}

// ---------------- split / transpose-split kernels ----------------------------
__global__ void split_a(const float* __restrict__ in,
                        __nv_bfloat16* __restrict__ hi,
                        __nv_bfloat16* __restrict__ lo, int n4)
{
    int i = blockIdx.x * blockDim.x + threadIdx.x;
    if (i >= n4) return;
    float4 v = ((const float4*)in)[i];
    uint32_t h0, l0, h1, l1;
    pack_hilo(v.x, v.y, h0, l0);
    pack_hilo(v.z, v.w, h1, l1);
    ((uint32_t*)hi)[i*2]   = h0;  ((uint32_t*)hi)[i*2+1] = h1;
    ((uint32_t*)lo)[i*2]   = l0;  ((uint32_t*)lo)[i*2+1] = l1;
}

// W[R,C] fp32 -> T[C,R] bf16 hi/lo
__global__ void transpose_split(const float* __restrict__ W,
                                __nv_bfloat16* __restrict__ Thi,
                                __nv_bfloat16* __restrict__ Tlo, int R, int C)
{
    __shared__ float t[32][33];
    int c0 = blockIdx.x * 32, r0 = blockIdx.y * 32;
    int tx = threadIdx.x, ty = threadIdx.y;
#pragma unroll
    for (int j = 0; j < 4; j++)
        t[ty + j*8][tx] = W[(size_t)(r0 + ty + j*8) * C + c0 + tx];
    __syncthreads();
#pragma unroll
    for (int j = 0; j < 4; j++) {
        int cc = c0 + ty + j*8;
        float v = t[tx][ty + j*8];
        __nv_bfloat16 h = __float2bfloat16(v);
        __nv_bfloat16 l = __float2bfloat16(v - __bfloat162float(h));
        Thi[(size_t)cc * R + r0 + tx] = h;
        Tlo[(size_t)cc * R + r0 + tx] = l;
    }
}

// V slice of g_qkv -> [bh, d, s] bf16 hi/lo
__global__ void v_transpose(const float* __restrict__ qkv)
{
    __shared__ float t[32][33];
    const int b = blockIdx.z >> 4, h = blockIdx.z & 15;
    const int d0 = blockIdx.x * 32, s0 = blockIdx.y * 32;
    const int tx = threadIdx.x, ty = threadIdx.y;
#pragma unroll
    for (int j = 0; j < 4; j++)
        t[ty + j*8][tx] = qkv[(size_t)(b * SEQ + s0 + ty + j*8) * QKVN
                              + 2*DM + h*DH + d0 + tx];
    __syncthreads();
#pragma unroll
    for (int j = 0; j < 4; j++) {
        int dd = d0 + ty + j*8;
        float v = t[tx][ty + j*8];                     // V[s0+tx][dd]
        __nv_bfloat16 hh = __float2bfloat16(v);
        __nv_bfloat16 ll = __float2bfloat16(v - __bfloat162float(hh));
        size_t o = ((size_t)blockIdx.z * DH + dd) * SEQ + s0 + tx;
        g_vthi[o] = hh;
        g_vtlo[o] = ll;
    }
}

// ---------------- RoPE -> bf16 hi/lo Q,K [bh,s,d] ----------------------------
__global__ void rope_split(const float* __restrict__ qkv,
                           const float* __restrict__ rc,
                           const float* __restrict__ rs)
{
    const int idx = blockIdx.x * blockDim.x + threadIdx.x;
    const int j = idx & (RH - 1);
    const int s = (idx >> 6) & (SEQ - 1);
    const int h = (idx >> 17) & (NH - 1);
    const int b = idx >> 21;

    const float* row = qkv + (size_t)(b * SEQ + s) * QKVN;
    const float c  = rc[s * RH + j];
    const float sn = rs[s * RH + j];
    const int col = h * DH + 2 * j;

    const float qe = row[col],      qo = row[col + 1];
    const float ke = row[DM + col], ko = row[DM + col + 1];

    const float q0 = qe * c - qo * sn, q1 = qe * sn + qo * c;
    const float k0 = ke * c - ko * sn, k1 = ke * sn + ko * c;

    const size_t o2 = (((size_t)((b * NH + h) * SEQ + s)) * DH + 2 * j) >> 1;
    uint32_t hi, lo;
    pack_hilo(q0, q1, hi, lo);
    ((uint32_t*)g_qhi)[o2] = hi; ((uint32_t*)g_qlo)[o2] = lo;
    pack_hilo(k0, k1, hi, lo);
    ((uint32_t*)g_khi)[o2] = hi; ((uint32_t*)g_klo)[o2] = lo;
}

// ---------------- bf16x3 GEMM via mma.sync -----------------------------------
// C[M,N] = A[M,K] @ B^T (B stored [N,K] K-major) + bias.
// 128x128 CTA tile, 8 warps (2x4), warp tile 64x32, K-chunk 32.
// XOR-swizzled 64B smem rows (no padding), 3-stage cp.async pipeline,
// single __syncthreads per iteration.  2 CTAs/SM.
#define TK 32
#define TILE_B (128*64)        // 8192
#define STAGE  (4*TILE_B)      // 32768: Ahi, Alo, Bhi, Blo
#define GEMM_SMEM (3*STAGE)    // 98304

// smem chunk swizzle: 4x 16B chunks per row; phys = c ^ ((row>>1)&3)
__device__ __forceinline__ uint32_t sw_off(int row, int c) {
    return (uint32_t)(row * 64 + ((c ^ ((row >> 1) & 3)) << 4));
}

__device__ __forceinline__ void gemm_load_stage(
    uint32_t st, const __nv_bfloat16* const* srcs, const int* rowb,
    int kt, int K, int tid)
{
#pragma unroll
    for (int it = 0; it < 8; it++) {
        int idx = it * 256 + tid;          // 2048 chunks of 16B
        int t = idx >> 9;                  // tile (512 chunks each)
        int rem = idx & 511;
        int r = rem >> 2, c = rem & 3;
        uint32_t dst = st + t * TILE_B + sw_off(r, c);
        const void* src = srcs[t] + (size_t)(rowb[t] + r) * K + kt + c * 8;
        CP_ASYNC16(dst, src);
    }
}

__global__ __launch_bounds__(256)
void gemm_tc(const __nv_bfloat16* __restrict__ Ahi, const __nv_bfloat16* __restrict__ Alo,
             const __nv_bfloat16* __restrict__ Bhi, const __nv_bfloat16* __restrict__ Blo,
             const float* __restrict__ bias, float* __restrict__ C,
             int M, int N, int K)
{
    extern __shared__ char sm[];
    const uint32_t sbase = smem_u32(sm);

    const int tid = threadIdx.x;
    const int wid = tid >> 5;
    const int lane = tid & 31;
    const int warpM = wid >> 2;
    const int warpN = wid & 3;
    const int bn = blockIdx.x * 128;
    const int bm = blockIdx.y * 128;

    const __nv_bfloat16* srcs[4] = {Ahi, Alo, Bhi, Blo};
    const int rowb[4] = {bm, bm, bn, bn};

    float acc[4][4][4];
#pragma unroll
    for (int mi = 0; mi < 4; mi++)
#pragma unroll
        for (int ni = 0; ni < 4; ni++)
#pragma unroll
            for (int r = 0; r < 4; r++) acc[mi][ni][r] = 0.f;

    const int NI = K / TK;

    // prologue: stages 0, 1
    gemm_load_stage(sbase, srcs, rowb, 0, K, tid);
    CP_COMMIT();
    gemm_load_stage(sbase + STAGE, srcs, rowb, TK, K, tid);
    CP_COMMIT();

    int buf = 0;
    for (int i = 0; i < NI; i++) {
        if (i + 1 < NI) { CP_WAIT(1); } else { CP_WAIT(0); }
        __syncthreads();

        if (i + 2 < NI) {
            int nb = buf + 2; if (nb >= 3) nb -= 3;
            gemm_load_stage(sbase + nb * STAGE, srcs, rowb, (i + 2) * TK, K, tid);
            CP_COMMIT();
        }

        const uint32_t st = sbase + buf * STAGE;
        const uint32_t Ah = st, Al = st + TILE_B;
        const uint32_t Bh = st + 2 * TILE_B, Bl = st + 3 * TILE_B;
        const int ar = warpM * 64 + (lane & 15);
        const int br = warpN * 32 + (lane & 15);

#pragma unroll
        for (int ks = 0; ks < 2; ks++) {
            const int cc = ks * 2 + (lane >> 4);
            const uint32_t aoff = sw_off(ar, cc);
            const uint32_t boff = sw_off(br, cc);

            uint32_t ahf[4][4], alf[4][4], bhf[2][4], blf[2][4];
#pragma unroll
            for (int mi = 0; mi < 4; mi++) {
                ldsm_x4(ahf[mi], Ah + aoff + mi * 1024);
                ldsm_x4(alf[mi], Al + aoff + mi * 1024);
            }
#pragma unroll
            for (int pi = 0; pi < 2; pi++) {
                ldsm_x4(bhf[pi], Bh + boff + pi * 1024);
                ldsm_x4(blf[pi], Bl + boff + pi * 1024);
            }
#pragma unroll
            for (int mi = 0; mi < 4; mi++)
#pragma unroll
                for (int ni = 0; ni < 4; ni++) {
                    const int pi = ni >> 1, o = ni & 1;
                    mma_bf16(acc[mi][ni], ahf[mi], bhf[pi][o], bhf[pi][o + 2]);
                    mma_bf16(acc[mi][ni], ahf[mi], blf[pi][o], blf[pi][o + 2]);
                    mma_bf16(acc[mi][ni], alf[mi], bhf[pi][o], bhf[pi][o + 2]);
                }
        }
        buf++; if (buf >= 3) buf = 0;
    }

#pragma unroll
    for (int mi = 0; mi < 4; mi++) {
        const int r0 = bm + warpM * 64 + mi * 16 + (lane >> 2);
#pragma unroll
        for (int ni = 0; ni < 4; ni++) {
            const int c0 = bn + warpN * 32 + ni * 8 + (lane & 3) * 2;
            const float b0 = bias[c0], b1 = bias[c0 + 1];
            float2 v0 = make_float2(acc[mi][ni][0] + b0, acc[mi][ni][1] + b1);
            float2 v1 = make_float2(acc[mi][ni][2] + b0, acc[mi][ni][3] + b1);
            *(float2*)(C + (size_t)r0 * N + c0) = v0;
            *(float2*)(C + (size_t)(r0 + 8) * N + c0) = v1;
        }
    }
}

// ---------------- HMMA flash attention (unchanged from R4) -------------------
#define KSTR 272
#define VSTR 144
#define KTILE (64*KSTR)
#define VTILE (128*VSTR)
#define ASTAGE (2*KTILE + 2*VTILE)
#define QSTR 272
#define QTILE (128*QSTR)
#define ATTN_SMEM (2*QTILE + 2*ASTAGE)  // 212992

__device__ __forceinline__ void attn_load_kv(uint32_t st, int bh, int k0, int tid)
{
    const __nv_bfloat16* kh = g_khi;
    const __nv_bfloat16* kl = g_klo;
    const __nv_bfloat16* vh = g_vthi;
    const __nv_bfloat16* vl = g_vtlo;
#pragma unroll
    for (int it = 0; it < 16; it++) {
        int idx = it * 256 + tid;
        int sec = idx >> 10, rem = idx & 1023;
        if (sec < 2) {
            int r = rem >> 4, c = rem & 15;
            uint32_t dst = st + sec * KTILE + r * KSTR + c * 16;
            const void* src = (sec ? kl : kh) + ((size_t)bh * SEQ + k0 + r) * DH + c * 8;
            CP_ASYNC16(dst, src);
        } else {
            int r = rem >> 3, c = rem & 7;
            uint32_t dst = st + 2 * KTILE + (sec - 2) * VTILE + r * VSTR + c * 16;
            const void* src = (sec == 2 ? vh : vl) + ((size_t)bh * DH + r) * SEQ + k0 + c * 8;
            CP_ASYNC16(dst, src);
        }
    }
}

__global__ __launch_bounds__(256, 1)
void attn_hmma()
{
    extern __shared__ char sm[];
    const uint32_t sbase = smem_u32(sm);
    const uint32_t qb_smem = sbase;
    const uint32_t stage0 = sbase + 2 * QTILE;

    const int qb = 15 - blockIdx.x;
    const int h = blockIdx.y, b = blockIdx.z;
    const int bh = b * NH + h;
    const int q0 = qb * 128;
    const int tid = threadIdx.x;
    const int w = tid >> 5;
    const int lane = tid & 31;
    const float scale = 0.08838834764831845f;

#pragma unroll
    for (int it = 0; it < 16; it++) {
        int idx = it * 256 + tid;
        int sec = idx >> 11, rem = idx & 2047;
        int r = rem >> 4, c = rem & 15;
        uint32_t dst = qb_smem + sec * QTILE + r * QSTR + c * 16;
        const void* src = (sec ? g_qlo : g_qhi) + ((size_t)bh * SEQ + q0 + r) * DH + c * 8;
        CP_ASYNC16(dst, src);
    }
    CP_COMMIT();
    CP_WAIT(0);
    __syncthreads();

    uint32_t qh[8][4], ql[8][4];
    {
        const uint32_t arow = (w * 16 + (lane & 15)) * QSTR + (lane >> 4) * 16;
#pragma unroll
        for (int kt = 0; kt < 8; kt++) {
            ldsm_x4(qh[kt], qb_smem + arow + kt * 32);
            ldsm_x4(ql[kt], qb_smem + QTILE + arow + kt * 32);
        }
    }

    float oa[16][4];
#pragma unroll
    for (int dt = 0; dt < 16; dt++)
#pragma unroll
        for (int r = 0; r < 4; r++) oa[dt][r] = 0.f;
    float m0 = -1e30f, m1 = -1e30f, l0 = 0.f, l1 = 0.f;

    const int nch = 2 * qb + 2;

    attn_load_kv(stage0, bh, 0, tid);
    CP_COMMIT();

    for (int kb = 0; kb < nch; kb++) {
        if (kb + 1 < nch) {
            attn_load_kv(stage0 + ((kb + 1) & 1) * ASTAGE, bh, (kb + 1) * 64, tid);
            CP_COMMIT();
            CP_WAIT(1);
        } else {
            CP_WAIT(0);
        }
        __syncthreads();

        const uint32_t st = stage0 + (kb & 1) * ASTAGE;
        const int k0 = kb * 64;

        float e[8][4];
#pragma unroll
        for (int nt = 0; nt < 8; nt++)
#pragma unroll
            for (int r = 0; r < 4; r++) e[nt][r] = 0.f;

#pragma unroll
        for (int kt = 0; kt < 8; kt++) {
            const uint32_t ko = kt * 32 + (lane >> 4) * 16;
#pragma unroll
            for (int np = 0; np < 4; np++) {
                const uint32_t brow = (np * 16 + (lane & 15)) * KSTR + ko;
                uint32_t bhf[4], blf[4];
                ldsm_x4(bhf, st + brow);
                ldsm_x4(blf, st + KTILE + brow);
#pragma unroll
                for (int o = 0; o < 2; o++) {
                    const int nt = 2 * np + o;
                    mma_bf16(e[nt], qh[kt], bhf[o], bhf[o + 2]);
                    mma_bf16(e[nt], qh[kt], blf[o], blf[o + 2]);
                    mma_bf16(e[nt], ql[kt], bhf[o], bhf[o + 2]);
                }
            }
        }

#pragma unroll
        for (int nt = 0; nt < 8; nt++)
#pragma unroll
            for (int r = 0; r < 4; r++) e[nt][r] *= scale;

        const int row0 = q0 + w * 16 + (lane >> 2);
        if (kb >= 2 * qb) {
#pragma unroll
            for (int nt = 0; nt < 8; nt++) {
                const int col = k0 + nt * 8 + (lane & 3) * 2;
                if (col     > row0)     e[nt][0] = -1e30f;
                if (col + 1 > row0)     e[nt][1] = -1e30f;
                if (col     > row0 + 8) e[nt][2] = -1e30f;
                if (col + 1 > row0 + 8) e[nt][3] = -1e30f;
            }
        }

        float rm0 = e[0][0], rm1 = e[0][2];
#pragma unroll
        for (int nt = 0; nt < 8; nt++) {
            rm0 = fmaxf(rm0, fmaxf(e[nt][0], e[nt][1]));
            rm1 = fmaxf(rm1, fmaxf(e[nt][2], e[nt][3]));
        }
        rm0 = fmaxf(rm0, __shfl_xor_sync(0xffffffffu, rm0, 1));
        rm0 = fmaxf(rm0, __shfl_xor_sync(0xffffffffu, rm0, 2));
        rm1 = fmaxf(rm1, __shfl_xor_sync(0xffffffffu, rm1, 1));
        rm1 = fmaxf(rm1, __shfl_xor_sync(0xffffffffu, rm1, 2));

        const float mn0 = fmaxf(m0, rm0), mn1 = fmaxf(m1, rm1);
        const float al0 = __expf(m0 - mn0), al1 = __expf(m1 - mn1);
        m0 = mn0; m1 = mn1;

        float s0 = 0.f, s1 = 0.f;
#pragma unroll
        for (int nt = 0; nt < 8; nt++) {
            e[nt][0] = __expf(e[nt][0] - mn0);
            e[nt][1] = __expf(e[nt][1] - mn0);
            e[nt][2] = __expf(e[nt][2] - mn1);
            e[nt][3] = __expf(e[nt][3] - mn1);
            s0 += e[nt][0] + e[nt][1];
            s1 += e[nt][2] + e[nt][3];
        }
        s0 += __shfl_xor_sync(0xffffffffu, s0, 1);
        s0 += __shfl_xor_sync(0xffffffffu, s0, 2);
        s1 += __shfl_xor_sync(0xffffffffu, s1, 1);
        s1 += __shfl_xor_sync(0xffffffffu, s1, 2);
        l0 = l0 * al0 + s0;
        l1 = l1 * al1 + s1;

#pragma unroll
        for (int dt = 0; dt < 16; dt++) {
            oa[dt][0] *= al0; oa[dt][1] *= al0;
            oa[dt][2] *= al1; oa[dt][3] *= al1;
        }

        const uint32_t vb = st + 2 * KTILE;
#pragma unroll
        for (int kt2 = 0; kt2 < 4; kt2++) {
            const int ta = 2 * kt2, tb = ta + 1;
            uint32_t ph[4], pl[4];
            pack_hilo(e[ta][0], e[ta][1], ph[0], pl[0]);
            pack_hilo(e[ta][2], e[ta][3], ph[1], pl[1]);
            pack_hilo(e[tb][0], e[tb][1], ph[2], pl[2]);
            pack_hilo(e[tb][2], e[tb][3], ph[3], pl[3]);

            const uint32_t ko = kt2 * 32 + (lane >> 4) * 16;
#pragma unroll
            for (int np = 0; np < 8; np++) {
                const uint32_t brow = (np * 16 + (lane & 15)) * VSTR + ko;
                uint32_t bhf[4], blf[4];
                ldsm_x4(bhf, vb + brow);
                ldsm_x4(blf, vb + VTILE + brow);
#pragma unroll
                for (int o = 0; o < 2; o++) {
                    const int dt = 2 * np + o;
                    mma_bf16(oa[dt], ph, bhf[o], bhf[o + 2]);
                    mma_bf16(oa[dt], ph, blf[o], blf[o + 2]);
                    mma_bf16(oa[dt], pl, bhf[o], bhf[o + 2]);
                }
            }
        }
        __syncthreads();
    }

    const float inv0 = 1.f / l0, inv1 = 1.f / l1;
    const size_t tokA = (size_t)b * SEQ + q0 + w * 16 + (lane >> 2);
    const size_t tokB = tokA + 8;
    const int colb = h * DH + (lane & 3) * 2;
    uint32_t* ahi = (uint32_t*)g_ahi;
    uint32_t* alo = (uint32_t*)g_alo;
#pragma unroll
    for (int dt = 0; dt < 16; dt++) {
        const int col = colb + dt * 8;
        uint32_t hi, lo;
        pack_hilo(oa[dt][0] * inv0, oa[dt][1] * inv0, hi, lo);
        ahi[(tokA * DM + col) >> 1] = hi;
        alo[(tokA * DM + col) >> 1] = lo;
        pack_hilo(oa[dt][2] * inv1, oa[dt][3] * inv1, hi, lo);
        ahi[(tokB * DM + col) >> 1] = hi;
        alo[(tokB * DM + col) >> 1] = lo;
    }
}

// ---------------- launch -----------------------------------------------------
extern "C" void kernel_launch(void* const* d_in, const int* in_sizes, int n_in,
                              void* d_out, int out_size)
{
    const float* x     = (const float*)d_in[0];
    const float* w_qkv = (const float*)d_in[1];
    const float* b_qkv = (const float*)d_in[2];
    const float* w_out = (const float*)d_in[3];
    const float* b_out = (const float*)d_in[4];
    const float* rc    = (const float*)d_in[5];
    const float* rs    = (const float*)d_in[6];
    float* out = (float*)d_out;

    float* p_qkv;
    __nv_bfloat16 *p_xhi, *p_xlo, *p_ahi, *p_alo;
    __nv_bfloat16 *p_wqh, *p_wql, *p_woh, *p_wol;
    cudaGetSymbolAddress((void**)&p_qkv, g_qkv);
    cudaGetSymbolAddress((void**)&p_xhi, g_xhi);
    cudaGetSymbolAddress((void**)&p_xlo, g_xlo);
    cudaGetSymbolAddress((void**)&p_ahi, g_ahi);
    cudaGetSymbolAddress((void**)&p_alo, g_alo);
    cudaGetSymbolAddress((void**)&p_wqh, g_wqkvT_hi);
    cudaGetSymbolAddress((void**)&p_wql, g_wqkvT_lo);
    cudaGetSymbolAddress((void**)&p_woh, g_woutT_hi);
    cudaGetSymbolAddress((void**)&p_wol, g_woutT_lo);

    cudaFuncSetAttribute(gemm_tc,
                         cudaFuncAttributeMaxDynamicSharedMemorySize, GEMM_SMEM);
    cudaFuncSetAttribute(attn_hmma,
                         cudaFuncAttributeMaxDynamicSharedMemorySize, ATTN_SMEM);

    // 1) split x -> bf16 hi/lo
    {
        int n4 = NTOK * DM / 4;
        split_a<<<(n4 + 255) / 256, 256>>>(x, p_xhi, p_xlo, n4);
    }
    // 2) transpose+split weights
    transpose_split<<<dim3(QKVN / 32, DM / 32), dim3(32, 8)>>>(w_qkv, p_wqh, p_wql, DM, QKVN);
    transpose_split<<<dim3(DM / 32, DM / 32), dim3(32, 8)>>>(w_out, p_woh, p_wol, DM, DM);
    // 3) qkv = x @ w_qkv + b  (HMMA bf16x3, 128x128 tiles, 3-stage)
    gemm_tc<<<dim3(QKVN / 128, NTOK / 128), 256, GEMM_SMEM>>>(
        p_xhi, p_xlo, p_wqh, p_wql, b_qkv, p_qkv, NTOK, QKVN, DM);
    // 4) RoPE -> bf16 hi/lo Q,K ; V transpose -> [bh,d,s]
    rope_split<<<(BATCH * NH * SEQ * RH) / 256, 256>>>(p_qkv, rc, rs);
    v_transpose<<<dim3(DH / 32, SEQ / 32, BH), dim3(32, 8)>>>(p_qkv);
    // 5) HMMA flash attention -> g_ahi/g_alo
    attn_hmma<<<dim3(SEQ / 128, NH, BATCH), 256, ATTN_SMEM>>>();
    // 6) out = att @ w_out + b  (HMMA bf16x3)
    gemm_tc<<<dim3(DM / 128, NTOK / 128), 256, GEMM_SMEM>>>(
        p_ahi, p_alo, p_woh, p_wol, b_out, out, NTOK, DM, DM);
}

// round 7
// speedup vs baseline: 1.2422x; 1.0140x over previous
#include <cuda_runtime.h>
#include <cuda_bf16.h>
#include <cstdint>
#include <math.h>

// Problem constants
#define BATCH 4
#define SEQ   2048
#define DM    2048
#define NH    16
#define DH    128
#define RH    64
#define NTOK  (BATCH*SEQ)      // 8192
#define QKVN  (3*DM)           // 6144
#define BH    (BATCH*NH)       // 64

// ---------------- scratch (device globals) ----------------------------------
__device__ float g_qkv[(size_t)NTOK * QKVN];

__device__ __nv_bfloat16 g_xhi[(size_t)NTOK*DM];
__device__ __nv_bfloat16 g_xlo[(size_t)NTOK*DM];
__device__ __nv_bfloat16 g_ahi[(size_t)NTOK*DM];
__device__ __nv_bfloat16 g_alo[(size_t)NTOK*DM];
__device__ __nv_bfloat16 g_wqkvT_hi[(size_t)QKVN*DM];
__device__ __nv_bfloat16 g_wqkvT_lo[(size_t)QKVN*DM];
__device__ __nv_bfloat16 g_woutT_hi[(size_t)DM*DM];
__device__ __nv_bfloat16 g_woutT_lo[(size_t)DM*DM];

// attention operands, bf16 hi/lo
__device__ __nv_bfloat16 g_qhi[(size_t)BH*SEQ*DH];
__device__ __nv_bfloat16 g_qlo[(size_t)BH*SEQ*DH];
__device__ __nv_bfloat16 g_khi[(size_t)BH*SEQ*DH];
__device__ __nv_bfloat16 g_klo[(size_t)BH*SEQ*DH];
__device__ __nv_bfloat16 g_vthi[(size_t)BH*DH*SEQ];   // [bh, d, s]
__device__ __nv_bfloat16 g_vtlo[(size_t)BH*DH*SEQ];

// ---------------- PTX helpers -------------------------------------------------
__device__ __forceinline__ uint32_t smem_u32(const void* p) {
    uint32_t a;
    asm("{ .reg .u64 t; cvta.to.shared.u64 t, %1; cvt.u32.u64 %0, t; }" : "=r"(a) : "l"(p));
    return a;
}
#define CP_ASYNC16(dst, src) \
    asm volatile("cp.async.cg.shared.global [%0], [%1], 16;" :: "r"(dst), "l"(src))
#define CP_COMMIT() asm volatile("cp.async.commit_group;" ::: "memory")
#define CP_WAIT(n)  asm volatile("cp.async.wait_group %0;" :: "n"(n) : "memory")

__device__ __forceinline__ void ldsm_x4(uint32_t* r, uint32_t addr) {
    asm volatile("ldmatrix.sync.aligned.m8n8.x4.shared.b16 {%0,%1,%2,%3}, [%4];"
        : "=r"(r[0]), "=r"(r[1]), "=r"(r[2]), "=r"(r[3]) : "r"(addr));
}
__device__ __forceinline__ void mma_bf16(float* d, const uint32_t* a,
                                         uint32_t b0, uint32_t b1) {
    asm volatile("mma.sync.aligned.m16n8k16.row.col.f32.bf16.bf16.f32 "
        "{%0,%1,%2,%3}, {%4,%5,%6,%7}, {%8,%9}, {%0,%1,%2,%3};"
        : "+f"(d[0]), "+f"(d[1]), "+f"(d[2]), "+f"(d[3])
        : "r"(a[0]), "r"(a[1]), "r"(a[2]), "r"(a[3]), "r"(b0), "r"(b1));
}
__device__ __forceinline__ void pack_hilo(float x, float y, uint32_t& hi, uint32_t& lo) {
    __nv_bfloat162 h = __floats2bfloat162_rn(x, y);
    float rx = x - __bfloat162float(h.x);
    float ry = y - __bfloat162float(h.y);
    __nv_bfloat162 l = __floats2bfloat162_rn(rx, ry);
    hi = *reinterpret_cast<uint32_t*>(&h);
    lo = *reinterpret_cast<uint32_t*>(&l);
}

// ---------------- split / transpose-split kernels ----------------------------
__global__ void split_a(const float* __restrict__ in,
                        __nv_bfloat16* __restrict__ hi,
                        __nv_bfloat16* __restrict__ lo, int n4)
{
    int i = blockIdx.x * blockDim.x + threadIdx.x;
    if (i >= n4) return;
    float4 v = ((const float4*)in)[i];
    uint32_t h0, l0, h1, l1;
    pack_hilo(v.x, v.y, h0, l0);
    pack_hilo(v.z, v.w, h1, l1);
    ((uint32_t*)hi)[i*2]   = h0;  ((uint32_t*)hi)[i*2+1] = h1;
    ((uint32_t*)lo)[i*2]   = l0;  ((uint32_t*)lo)[i*2+1] = l1;
}

// W[R,C] fp32 -> T[C,R] bf16 hi/lo
__global__ void transpose_split(const float* __restrict__ W,
                                __nv_bfloat16* __restrict__ Thi,
                                __nv_bfloat16* __restrict__ Tlo, int R, int C)
{
    __shared__ float t[32][33];
    int c0 = blockIdx.x * 32, r0 = blockIdx.y * 32;
    int tx = threadIdx.x, ty = threadIdx.y;
#pragma unroll
    for (int j = 0; j < 4; j++)
        t[ty + j*8][tx] = W[(size_t)(r0 + ty + j*8) * C + c0 + tx];
    __syncthreads();
#pragma unroll
    for (int j = 0; j < 4; j++) {
        int cc = c0 + ty + j*8;
        float v = t[tx][ty + j*8];
        __nv_bfloat16 h = __float2bfloat16(v);
        __nv_bfloat16 l = __float2bfloat16(v - __bfloat162float(h));
        Thi[(size_t)cc * R + r0 + tx] = h;
        Tlo[(size_t)cc * R + r0 + tx] = l;
    }
}

// V slice of g_qkv -> [bh, d, s] bf16 hi/lo
__global__ void v_transpose(const float* __restrict__ qkv)
{
    __shared__ float t[32][33];
    const int b = blockIdx.z >> 4, h = blockIdx.z & 15;
    const int d0 = blockIdx.x * 32, s0 = blockIdx.y * 32;
    const int tx = threadIdx.x, ty = threadIdx.y;
#pragma unroll
    for (int j = 0; j < 4; j++)
        t[ty + j*8][tx] = qkv[(size_t)(b * SEQ + s0 + ty + j*8) * QKVN
                              + 2*DM + h*DH + d0 + tx];
    __syncthreads();
#pragma unroll
    for (int j = 0; j < 4; j++) {
        int dd = d0 + ty + j*8;
        float v = t[tx][ty + j*8];                     // V[s0+tx][dd]
        __nv_bfloat16 hh = __float2bfloat16(v);
        __nv_bfloat16 ll = __float2bfloat16(v - __bfloat162float(hh));
        size_t o = ((size_t)blockIdx.z * DH + dd) * SEQ + s0 + tx;
        g_vthi[o] = hh;
        g_vtlo[o] = ll;
    }
}

// ---------------- RoPE -> bf16 hi/lo Q,K [bh,s,d] ----------------------------
__global__ void rope_split(const float* __restrict__ qkv,
                           const float* __restrict__ rc,
                           const float* __restrict__ rs)
{
    const int idx = blockIdx.x * blockDim.x + threadIdx.x;
    const int j = idx & (RH - 1);
    const int s = (idx >> 6) & (SEQ - 1);
    const int h = (idx >> 17) & (NH - 1);
    const int b = idx >> 21;

    const float* row = qkv + (size_t)(b * SEQ + s) * QKVN;
    const float c  = rc[s * RH + j];
    const float sn = rs[s * RH + j];
    const int col = h * DH + 2 * j;

    const float qe = row[col],      qo = row[col + 1];
    const float ke = row[DM + col], ko = row[DM + col + 1];

    const float q0 = qe * c - qo * sn, q1 = qe * sn + qo * c;
    const float k0 = ke * c - ko * sn, k1 = ke * sn + ko * c;

    const size_t o2 = (((size_t)((b * NH + h) * SEQ + s)) * DH + 2 * j) >> 1;
    uint32_t hi, lo;
    pack_hilo(q0, q1, hi, lo);
    ((uint32_t*)g_qhi)[o2] = hi; ((uint32_t*)g_qlo)[o2] = lo;
    pack_hilo(k0, k1, hi, lo);
    ((uint32_t*)g_khi)[o2] = hi; ((uint32_t*)g_klo)[o2] = lo;
}

// ---------------- bf16x3 GEMM via mma.sync -----------------------------------
// C[M,N] = A[M,K] @ B^T (B stored [N,K] K-major) + bias.
// 128x128 CTA tile, 4 warps (2x2), warp tile 64x64, K-chunk 32.
// XOR-swizzled 64B smem rows, 3-stage cp.async pipeline, 2 CTAs/SM.
// Larger warp tiles cut ldmatrix redundancy: 96KB -> 64KB reads per CTA-stage.
#define TK 32
#define TILE_B (128*64)        // 8192
#define STAGE  (4*TILE_B)      // 32768: Ahi, Alo, Bhi, Blo
#define GEMM_SMEM (3*STAGE)    // 98304

// smem chunk swizzle: 4x 16B chunks per row; phys = c ^ ((row>>1)&3)
__device__ __forceinline__ uint32_t sw_off(int row, int c) {
    return (uint32_t)(row * 64 + ((c ^ ((row >> 1) & 3)) << 4));
}

__device__ __forceinline__ void gemm_load_stage(
    uint32_t st, const __nv_bfloat16* const* srcs, const int* rowb,
    int kt, int K, int tid)
{
#pragma unroll
    for (int it = 0; it < 16; it++) {
        int idx = it * 128 + tid;          // 2048 chunks of 16B
        int t = idx >> 9;                  // tile (512 chunks each)
        int rem = idx & 511;
        int r = rem >> 2, c = rem & 3;
        uint32_t dst = st + t * TILE_B + sw_off(r, c);
        const void* src = srcs[t] + (size_t)(rowb[t] + r) * K + kt + c * 8;
        CP_ASYNC16(dst, src);
    }
}

__global__ __launch_bounds__(128)
void gemm_tc(const __nv_bfloat16* __restrict__ Ahi, const __nv_bfloat16* __restrict__ Alo,
             const __nv_bfloat16* __restrict__ Bhi, const __nv_bfloat16* __restrict__ Blo,
             const float* __restrict__ bias, float* __restrict__ C,
             int M, int N, int K)
{
    extern __shared__ char sm[];
    const uint32_t sbase = smem_u32(sm);

    const int tid = threadIdx.x;
    const int wid = tid >> 5;
    const int lane = tid & 31;
    const int warpM = wid >> 1;        // 0..1 (64 rows each)
    const int warpN = wid & 1;         // 0..1 (64 cols each)
    const int bn = blockIdx.x * 128;
    const int bm = blockIdx.y * 128;

    const __nv_bfloat16* srcs[4] = {Ahi, Alo, Bhi, Blo};
    const int rowb[4] = {bm, bm, bn, bn};

    float acc[4][8][4];
#pragma unroll
    for (int mi = 0; mi < 4; mi++)
#pragma unroll
        for (int ni = 0; ni < 8; ni++)
#pragma unroll
            for (int r = 0; r < 4; r++) acc[mi][ni][r] = 0.f;

    const int NI = K / TK;

    // prologue: stages 0, 1
    gemm_load_stage(sbase, srcs, rowb, 0, K, tid);
    CP_COMMIT();
    gemm_load_stage(sbase + STAGE, srcs, rowb, TK, K, tid);
    CP_COMMIT();

    int buf = 0;
    for (int i = 0; i < NI; i++) {
        if (i + 1 < NI) { CP_WAIT(1); } else { CP_WAIT(0); }
        __syncthreads();

        if (i + 2 < NI) {
            int nb = buf + 2; if (nb >= 3) nb -= 3;
            gemm_load_stage(sbase + nb * STAGE, srcs, rowb, (i + 2) * TK, K, tid);
            CP_COMMIT();
        }

        const uint32_t st = sbase + buf * STAGE;
        const uint32_t Ah = st, Al = st + TILE_B;
        const uint32_t Bh = st + 2 * TILE_B, Bl = st + 3 * TILE_B;
        const int ar = warpM * 64 + (lane & 15);
        const int br = warpN * 64 + (lane & 15);

#pragma unroll
        for (int ks = 0; ks < 2; ks++) {
            const int cc = ks * 2 + (lane >> 4);
            const uint32_t aoff = sw_off(ar, cc);
            const uint32_t boff = sw_off(br, cc);

            // A fragments (live across the np loop): 32 regs
            uint32_t ahf[4][4], alf[4][4];
#pragma unroll
            for (int mi = 0; mi < 4; mi++) {
                ldsm_x4(ahf[mi], Ah + aoff + mi * 1024);
                ldsm_x4(alf[mi], Al + aoff + mi * 1024);
            }
            // B fragments per 16-col group (transient)
#pragma unroll
            for (int np = 0; np < 4; np++) {
                uint32_t bhf[4], blf[4];
                ldsm_x4(bhf, Bh + boff + np * 1024);
                ldsm_x4(blf, Bl + boff + np * 1024);
#pragma unroll
                for (int mi = 0; mi < 4; mi++)
#pragma unroll
                    for (int o = 0; o < 2; o++) {
                        const int ni = np * 2 + o;
                        mma_bf16(acc[mi][ni], ahf[mi], bhf[o], bhf[o + 2]);
                        mma_bf16(acc[mi][ni], ahf[mi], blf[o], blf[o + 2]);
                        mma_bf16(acc[mi][ni], alf[mi], bhf[o], bhf[o + 2]);
                    }
            }
        }
        buf++; if (buf >= 3) buf = 0;
    }

#pragma unroll
    for (int mi = 0; mi < 4; mi++) {
        const int r0 = bm + warpM * 64 + mi * 16 + (lane >> 2);
#pragma unroll
        for (int ni = 0; ni < 8; ni++) {
            const int c0 = bn + warpN * 64 + ni * 8 + (lane & 3) * 2;
            const float b0 = bias[c0], b1 = bias[c0 + 1];
            float2 v0 = make_float2(acc[mi][ni][0] + b0, acc[mi][ni][1] + b1);
            float2 v1 = make_float2(acc[mi][ni][2] + b0, acc[mi][ni][3] + b1);
            *(float2*)(C + (size_t)r0 * N + c0) = v0;
            *(float2*)(C + (size_t)(r0 + 8) * N + c0) = v1;
        }
    }
}

// ---------------- HMMA flash attention (unchanged from R4) -------------------
#define KSTR 272
#define VSTR 144
#define KTILE (64*KSTR)
#define VTILE (128*VSTR)
#define ASTAGE (2*KTILE + 2*VTILE)
#define QSTR 272
#define QTILE (128*QSTR)
#define ATTN_SMEM (2*QTILE + 2*ASTAGE)  // 212992

__device__ __forceinline__ void attn_load_kv(uint32_t st, int bh, int k0, int tid)
{
    const __nv_bfloat16* kh = g_khi;
    const __nv_bfloat16* kl = g_klo;
    const __nv_bfloat16* vh = g_vthi;
    const __nv_bfloat16* vl = g_vtlo;
#pragma unroll
    for (int it = 0; it < 16; it++) {
        int idx = it * 256 + tid;
        int sec = idx >> 10, rem = idx & 1023;
        if (sec < 2) {
            int r = rem >> 4, c = rem & 15;
            uint32_t dst = st + sec * KTILE + r * KSTR + c * 16;
            const void* src = (sec ? kl : kh) + ((size_t)bh * SEQ + k0 + r) * DH + c * 8;
            CP_ASYNC16(dst, src);
        } else {
            int r = rem >> 3, c = rem & 7;
            uint32_t dst = st + 2 * KTILE + (sec - 2) * VTILE + r * VSTR + c * 16;
            const void* src = (sec == 2 ? vh : vl) + ((size_t)bh * DH + r) * SEQ + k0 + c * 8;
            CP_ASYNC16(dst, src);
        }
    }
}

__global__ __launch_bounds__(256, 1)
void attn_hmma()
{
    extern __shared__ char sm[];
    const uint32_t sbase = smem_u32(sm);
    const uint32_t qb_smem = sbase;
    const uint32_t stage0 = sbase + 2 * QTILE;

    const int qb = 15 - blockIdx.x;
    const int h = blockIdx.y, b = blockIdx.z;
    const int bh = b * NH + h;
    const int q0 = qb * 128;
    const int tid = threadIdx.x;
    const int w = tid >> 5;
    const int lane = tid & 31;
    const float scale = 0.08838834764831845f;

#pragma unroll
    for (int it = 0; it < 16; it++) {
        int idx = it * 256 + tid;
        int sec = idx >> 11, rem = idx & 2047;
        int r = rem >> 4, c = rem & 15;
        uint32_t dst = qb_smem + sec * QTILE + r * QSTR + c * 16;
        const void* src = (sec ? g_qlo : g_qhi) + ((size_t)bh * SEQ + q0 + r) * DH + c * 8;
        CP_ASYNC16(dst, src);
    }
    CP_COMMIT();
    CP_WAIT(0);
    __syncthreads();

    uint32_t qh[8][4], ql[8][4];
    {
        const uint32_t arow = (w * 16 + (lane & 15)) * QSTR + (lane >> 4) * 16;
#pragma unroll
        for (int kt = 0; kt < 8; kt++) {
            ldsm_x4(qh[kt], qb_smem + arow + kt * 32);
            ldsm_x4(ql[kt], qb_smem + QTILE + arow + kt * 32);
        }
    }

    float oa[16][4];
#pragma unroll
    for (int dt = 0; dt < 16; dt++)
#pragma unroll
        for (int r = 0; r < 4; r++) oa[dt][r] = 0.f;
    float m0 = -1e30f, m1 = -1e30f, l0 = 0.f, l1 = 0.f;

    const int nch = 2 * qb + 2;

    attn_load_kv(stage0, bh, 0, tid);
    CP_COMMIT();

    for (int kb = 0; kb < nch; kb++) {
        if (kb + 1 < nch) {
            attn_load_kv(stage0 + ((kb + 1) & 1) * ASTAGE, bh, (kb + 1) * 64, tid);
            CP_COMMIT();
            CP_WAIT(1);
        } else {
            CP_WAIT(0);
        }
        __syncthreads();

        const uint32_t st = stage0 + (kb & 1) * ASTAGE;
        const int k0 = kb * 64;

        float e[8][4];
#pragma unroll
        for (int nt = 0; nt < 8; nt++)
#pragma unroll
            for (int r = 0; r < 4; r++) e[nt][r] = 0.f;

#pragma unroll
        for (int kt = 0; kt < 8; kt++) {
            const uint32_t ko = kt * 32 + (lane >> 4) * 16;
#pragma unroll
            for (int np = 0; np < 4; np++) {
                const uint32_t brow = (np * 16 + (lane & 15)) * KSTR + ko;
                uint32_t bhf[4], blf[4];
                ldsm_x4(bhf, st + brow);
                ldsm_x4(blf, st + KTILE + brow);
#pragma unroll
                for (int o = 0; o < 2; o++) {
                    const int nt = 2 * np + o;
                    mma_bf16(e[nt], qh[kt], bhf[o], bhf[o + 2]);
                    mma_bf16(e[nt], qh[kt], blf[o], blf[o + 2]);
                    mma_bf16(e[nt], ql[kt], bhf[o], bhf[o + 2]);
                }
            }
        }

#pragma unroll
        for (int nt = 0; nt < 8; nt++)
#pragma unroll
            for (int r = 0; r < 4; r++) e[nt][r] *= scale;

        const int row0 = q0 + w * 16 + (lane >> 2);
        if (kb >= 2 * qb) {
#pragma unroll
            for (int nt = 0; nt < 8; nt++) {
                const int col = k0 + nt * 8 + (lane & 3) * 2;
                if (col     > row0)     e[nt][0] = -1e30f;
                if (col + 1 > row0)     e[nt][1] = -1e30f;
                if (col     > row0 + 8) e[nt][2] = -1e30f;
                if (col + 1 > row0 + 8) e[nt][3] = -1e30f;
            }
        }

        float rm0 = e[0][0], rm1 = e[0][2];
#pragma unroll
        for (int nt = 0; nt < 8; nt++) {
            rm0 = fmaxf(rm0, fmaxf(e[nt][0], e[nt][1]));
            rm1 = fmaxf(rm1, fmaxf(e[nt][2], e[nt][3]));
        }
        rm0 = fmaxf(rm0, __shfl_xor_sync(0xffffffffu, rm0, 1));
        rm0 = fmaxf(rm0, __shfl_xor_sync(0xffffffffu, rm0, 2));
        rm1 = fmaxf(rm1, __shfl_xor_sync(0xffffffffu, rm1, 1));
        rm1 = fmaxf(rm1, __shfl_xor_sync(0xffffffffu, rm1, 2));

        const float mn0 = fmaxf(m0, rm0), mn1 = fmaxf(m1, rm1);
        const float al0 = __expf(m0 - mn0), al1 = __expf(m1 - mn1);
        m0 = mn0; m1 = mn1;

        float s0 = 0.f, s1 = 0.f;
#pragma unroll
        for (int nt = 0; nt < 8; nt++) {
            e[nt][0] = __expf(e[nt][0] - mn0);
            e[nt][1] = __expf(e[nt][1] - mn0);
            e[nt][2] = __expf(e[nt][2] - mn1);
            e[nt][3] = __expf(e[nt][3] - mn1);
            s0 += e[nt][0] + e[nt][1];
            s1 += e[nt][2] + e[nt][3];
        }
        s0 += __shfl_xor_sync(0xffffffffu, s0, 1);
        s0 += __shfl_xor_sync(0xffffffffu, s0, 2);
        s1 += __shfl_xor_sync(0xffffffffu, s1, 1);
        s1 += __shfl_xor_sync(0xffffffffu, s1, 2);
        l0 = l0 * al0 + s0;
        l1 = l1 * al1 + s1;

#pragma unroll
        for (int dt = 0; dt < 16; dt++) {
            oa[dt][0] *= al0; oa[dt][1] *= al0;
            oa[dt][2] *= al1; oa[dt][3] *= al1;
        }

        const uint32_t vb = st + 2 * KTILE;
#pragma unroll
        for (int kt2 = 0; kt2 < 4; kt2++) {
            const int ta = 2 * kt2, tb = ta + 1;
            uint32_t ph[4], pl[4];
            pack_hilo(e[ta][0], e[ta][1], ph[0], pl[0]);
            pack_hilo(e[ta][2], e[ta][3], ph[1], pl[1]);
            pack_hilo(e[tb][0], e[tb][1], ph[2], pl[2]);
            pack_hilo(e[tb][2], e[tb][3], ph[3], pl[3]);

            const uint32_t ko = kt2 * 32 + (lane >> 4) * 16;
#pragma unroll
            for (int np = 0; np < 8; np++) {
                const uint32_t brow = (np * 16 + (lane & 15)) * VSTR + ko;
                uint32_t bhf[4], blf[4];
                ldsm_x4(bhf, vb + brow);
                ldsm_x4(blf, vb + VTILE + brow);
#pragma unroll
                for (int o = 0; o < 2; o++) {
                    const int dt = 2 * np + o;
                    mma_bf16(oa[dt], ph, bhf[o], bhf[o + 2]);
                    mma_bf16(oa[dt], ph, blf[o], blf[o + 2]);
                    mma_bf16(oa[dt], pl, bhf[o], bhf[o + 2]);
                }
            }
        }
        __syncthreads();
    }

    const float inv0 = 1.f / l0, inv1 = 1.f / l1;
    const size_t tokA = (size_t)b * SEQ + q0 + w * 16 + (lane >> 2);
    const size_t tokB = tokA + 8;
    const int colb = h * DH + (lane & 3) * 2;
    uint32_t* ahi = (uint32_t*)g_ahi;
    uint32_t* alo = (uint32_t*)g_alo;
#pragma unroll
    for (int dt = 0; dt < 16; dt++) {
        const int col = colb + dt * 8;
        uint32_t hi, lo;
        pack_hilo(oa[dt][0] * inv0, oa[dt][1] * inv0, hi, lo);
        ahi[(tokA * DM + col) >> 1] = hi;
        alo[(tokA * DM + col) >> 1] = lo;
        pack_hilo(oa[dt][2] * inv1, oa[dt][3] * inv1, hi, lo);
        ahi[(tokB * DM + col) >> 1] = hi;
        alo[(tokB * DM + col) >> 1] = lo;
    }
}

// ---------------- launch -----------------------------------------------------
extern "C" void kernel_launch(void* const* d_in, const int* in_sizes, int n_in,
                              void* d_out, int out_size)
{
    const float* x     = (const float*)d_in[0];
    const float* w_qkv = (const float*)d_in[1];
    const float* b_qkv = (const float*)d_in[2];
    const float* w_out = (const float*)d_in[3];
    const float* b_out = (const float*)d_in[4];
    const float* rc    = (const float*)d_in[5];
    const float* rs    = (const float*)d_in[6];
    float* out = (float*)d_out;

    float* p_qkv;
    __nv_bfloat16 *p_xhi, *p_xlo, *p_ahi, *p_alo;
    __nv_bfloat16 *p_wqh, *p_wql, *p_woh, *p_wol;
    cudaGetSymbolAddress((void**)&p_qkv, g_qkv);
    cudaGetSymbolAddress((void**)&p_xhi, g_xhi);
    cudaGetSymbolAddress((void**)&p_xlo, g_xlo);
    cudaGetSymbolAddress((void**)&p_ahi, g_ahi);
    cudaGetSymbolAddress((void**)&p_alo, g_alo);
    cudaGetSymbolAddress((void**)&p_wqh, g_wqkvT_hi);
    cudaGetSymbolAddress((void**)&p_wql, g_wqkvT_lo);
    cudaGetSymbolAddress((void**)&p_woh, g_woutT_hi);
    cudaGetSymbolAddress((void**)&p_wol, g_woutT_lo);

    cudaFuncSetAttribute(gemm_tc,
                         cudaFuncAttributeMaxDynamicSharedMemorySize, GEMM_SMEM);
    cudaFuncSetAttribute(attn_hmma,
                         cudaFuncAttributeMaxDynamicSharedMemorySize, ATTN_SMEM);

    // 1) split x -> bf16 hi/lo
    {
        int n4 = NTOK * DM / 4;
        split_a<<<(n4 + 255) / 256, 256>>>(x, p_xhi, p_xlo, n4);
    }
    // 2) transpose+split weights
    transpose_split<<<dim3(QKVN / 32, DM / 32), dim3(32, 8)>>>(w_qkv, p_wqh, p_wql, DM, QKVN);
    transpose_split<<<dim3(DM / 32, DM / 32), dim3(32, 8)>>>(w_out, p_woh, p_wol, DM, DM);
    // 3) qkv = x @ w_qkv + b  (HMMA bf16x3, 4-warp CTAs, 64x64 warp tiles)
    gemm_tc<<<dim3(QKVN / 128, NTOK / 128), 128, GEMM_SMEM>>>(
        p_xhi, p_xlo, p_wqh, p_wql, b_qkv, p_qkv, NTOK, QKVN, DM);
    // 4) RoPE -> bf16 hi/lo Q,K ; V transpose -> [bh,d,s]
    rope_split<<<(BATCH * NH * SEQ * RH) / 256, 256>>>(p_qkv, rc, rs);
    v_transpose<<<dim3(DH / 32, SEQ / 32, BH), dim3(32, 8)>>>(p_qkv);
    // 5) HMMA flash attention -> g_ahi/g_alo
    attn_hmma<<<dim3(SEQ / 128, NH, BATCH), 256, ATTN_SMEM>>>();
    // 6) out = att @ w_out + b  (HMMA bf16x3)
    gemm_tc<<<dim3(DM / 128, NTOK / 128), 128, GEMM_SMEM>>>(
        p_ahi, p_alo, p_woh, p_wol, b_out, out, NTOK, DM, DM);
}

// round 8
// speedup vs baseline: 1.7164x; 1.3817x over previous
#include <cuda_runtime.h>
#include <cuda_fp16.h>
#include <cstdint>
#include <math.h>

// Problem constants
#define BATCH 4
#define SEQ   2048
#define DM    2048
#define NH    16
#define DH    128
#define RH    64
#define NTOK  (BATCH*SEQ)      // 8192
#define QKVN  (3*DM)           // 6144
#define BH    (BATCH*NH)       // 64

// ---------------- scratch (device globals) ----------------------------------
__device__ float g_qkv[(size_t)NTOK * QKVN];

__device__ __half g_xhi[(size_t)NTOK*DM];
__device__ __half g_xlo[(size_t)NTOK*DM];
__device__ __half g_ahi[(size_t)NTOK*DM];
__device__ __half g_alo[(size_t)NTOK*DM];
__device__ __half g_wqkvT[(size_t)QKVN*DM];
__device__ __half g_woutT[(size_t)DM*DM];

// attention operands
__device__ __half g_qhi[(size_t)BH*SEQ*DH];
__device__ __half g_qlo[(size_t)BH*SEQ*DH];
__device__ __half g_k  [(size_t)BH*SEQ*DH];
__device__ __half g_vt [(size_t)BH*DH*SEQ];   // [bh, d, s]

// ---------------- PTX helpers -------------------------------------------------
__device__ __forceinline__ uint32_t smem_u32(const void* p) {
    uint32_t a;
    asm("{ .reg .u64 t; cvta.to.shared.u64 t, %1; cvt.u32.u64 %0, t; }" : "=r"(a) : "l"(p));
    return a;
}
#define CP_ASYNC16(dst, src) \
    asm volatile("cp.async.cg.shared.global [%0], [%1], 16;" :: "r"(dst), "l"(src))
#define CP_COMMIT() asm volatile("cp.async.commit_group;" ::: "memory")
#define CP_WAIT(n)  asm volatile("cp.async.wait_group %0;" :: "n"(n) : "memory")

__device__ __forceinline__ void ldsm_x4(uint32_t* r, uint32_t addr) {
    asm volatile("ldmatrix.sync.aligned.m8n8.x4.shared.b16 {%0,%1,%2,%3}, [%4];"
        : "=r"(r[0]), "=r"(r[1]), "=r"(r[2]), "=r"(r[3]) : "r"(addr));
}
__device__ __forceinline__ void mma_f16(float* d, const uint32_t* a,
                                        uint32_t b0, uint32_t b1) {
    asm volatile("mma.sync.aligned.m16n8k16.row.col.f32.f16.f16.f32 "
        "{%0,%1,%2,%3}, {%4,%5,%6,%7}, {%8,%9}, {%0,%1,%2,%3};"
        : "+f"(d[0]), "+f"(d[1]), "+f"(d[2]), "+f"(d[3])
        : "r"(a[0]), "r"(a[1]), "r"(a[2]), "r"(a[3]), "r"(b0), "r"(b1));
}
// fp16 hi/lo split of a float pair
__device__ __forceinline__ void pack_hilo(float x, float y, uint32_t& hi, uint32_t& lo) {
    __half2 h = __floats2half2_rn(x, y);
    float rx = x - __half2float(__low2half(h));
    float ry = y - __half2float(__high2half(h));
    __half2 l = __floats2half2_rn(rx, ry);
    hi = *reinterpret_cast<uint32_t*>(&h);
    lo = *reinterpret_cast<uint32_t*>(&l);
}
__device__ __forceinline__ uint32_t pack_f16(float x, float y) {
    __half2 h = __floats2half2_rn(x, y);
    return *reinterpret_cast<uint32_t*>(&h);
}

// ---------------- split / transpose kernels ----------------------------------
__global__ void split_a(const float* __restrict__ in,
                        __half* __restrict__ hi, __half* __restrict__ lo, int n4)
{
    int i = blockIdx.x * blockDim.x + threadIdx.x;
    if (i >= n4) return;
    float4 v = ((const float4*)in)[i];
    uint32_t h0, l0, h1, l1;
    pack_hilo(v.x, v.y, h0, l0);
    pack_hilo(v.z, v.w, h1, l1);
    ((uint32_t*)hi)[i*2]   = h0;  ((uint32_t*)hi)[i*2+1] = h1;
    ((uint32_t*)lo)[i*2]   = l0;  ((uint32_t*)lo)[i*2+1] = l1;
}

// W[R,C] fp32 -> T[C,R] fp16 (single rounding)
__global__ void transpose_w(const float* __restrict__ W,
                            __half* __restrict__ T, int R, int C)
{
    __shared__ float t[32][33];
    int c0 = blockIdx.x * 32, r0 = blockIdx.y * 32;
    int tx = threadIdx.x, ty = threadIdx.y;
#pragma unroll
    for (int j = 0; j < 4; j++)
        t[ty + j*8][tx] = W[(size_t)(r0 + ty + j*8) * C + c0 + tx];
    __syncthreads();
#pragma unroll
    for (int j = 0; j < 4; j++) {
        int cc = c0 + ty + j*8;
        T[(size_t)cc * R + r0 + tx] = __float2half_rn(t[tx][ty + j*8]);
    }
}

// V slice of g_qkv -> [bh, d, s] fp16
__global__ void v_transpose(const float* __restrict__ qkv)
{
    __shared__ float t[32][33];
    const int b = blockIdx.z >> 4, h = blockIdx.z & 15;
    const int d0 = blockIdx.x * 32, s0 = blockIdx.y * 32;
    const int tx = threadIdx.x, ty = threadIdx.y;
#pragma unroll
    for (int j = 0; j < 4; j++)
        t[ty + j*8][tx] = qkv[(size_t)(b * SEQ + s0 + ty + j*8) * QKVN
                              + 2*DM + h*DH + d0 + tx];
    __syncthreads();
#pragma unroll
    for (int j = 0; j < 4; j++) {
        int dd = d0 + ty + j*8;
        size_t o = ((size_t)blockIdx.z * DH + dd) * SEQ + s0 + tx;
        g_vt[o] = __float2half_rn(t[tx][ty + j*8]);
    }
}

// ---------------- RoPE -> fp16 Q hi/lo, K single [bh,s,d] --------------------
__global__ void rope_split(const float* __restrict__ qkv,
                           const float* __restrict__ rc,
                           const float* __restrict__ rs)
{
    const int idx = blockIdx.x * blockDim.x + threadIdx.x;
    const int j = idx & (RH - 1);
    const int s = (idx >> 6) & (SEQ - 1);
    const int h = (idx >> 17) & (NH - 1);
    const int b = idx >> 21;

    const float* row = qkv + (size_t)(b * SEQ + s) * QKVN;
    const float c  = rc[s * RH + j];
    const float sn = rs[s * RH + j];
    const int col = h * DH + 2 * j;

    const float qe = row[col],      qo = row[col + 1];
    const float ke = row[DM + col], ko = row[DM + col + 1];

    const float q0 = qe * c - qo * sn, q1 = qe * sn + qo * c;
    const float k0 = ke * c - ko * sn, k1 = ke * sn + ko * c;

    const size_t o2 = (((size_t)((b * NH + h) * SEQ + s)) * DH + 2 * j) >> 1;
    uint32_t hi, lo;
    pack_hilo(q0, q1, hi, lo);
    ((uint32_t*)g_qhi)[o2] = hi; ((uint32_t*)g_qlo)[o2] = lo;
    ((uint32_t*)g_k)[o2] = pack_f16(k0, k1);
}

// ---------------- fp16x2 GEMM via mma.sync -----------------------------------
// C[M,N] = A[M,K] @ B^T (B stored [N,K] K-major fp16) + bias.
// A split hi/lo fp16; C = Ah*B + Al*B (dropped A*Bl term ~1e-4 rel).
// 128x128 CTA tile, 4 warps (2x2), warp tile 64x64, K-chunk 32,
// XOR-swizzled 64B rows, 3-stage cp.async, 2 CTAs/SM.
#define TK 32
#define TILE_B (128*64)        // 8192
#define STAGE  (3*TILE_B)      // 24576: Ahi, Alo, B
#define GEMM_SMEM (3*STAGE)    // 73728

__device__ __forceinline__ uint32_t sw_off(int row, int c) {
    return (uint32_t)(row * 64 + ((c ^ ((row >> 1) & 3)) << 4));
}

__device__ __forceinline__ void gemm_load_stage(
    uint32_t st, const __half* const* srcs, const int* rowb,
    int kt, int K, int tid)
{
#pragma unroll
    for (int it = 0; it < 12; it++) {
        int idx = it * 128 + tid;          // 1536 chunks of 16B
        int t = idx >> 9;                  // tile (512 chunks each)
        int rem = idx & 511;
        int r = rem >> 2, c = rem & 3;
        uint32_t dst = st + t * TILE_B + sw_off(r, c);
        const void* src = srcs[t] + (size_t)(rowb[t] + r) * K + kt + c * 8;
        CP_ASYNC16(dst, src);
    }
}

__global__ __launch_bounds__(128)
void gemm_tc(const __half* __restrict__ Ahi, const __half* __restrict__ Alo,
             const __half* __restrict__ B,
             const float* __restrict__ bias, float* __restrict__ C,
             int M, int N, int K)
{
    extern __shared__ char sm[];
    const uint32_t sbase = smem_u32(sm);

    const int tid = threadIdx.x;
    const int wid = tid >> 5;
    const int lane = tid & 31;
    const int warpM = wid >> 1;
    const int warpN = wid & 1;
    const int bn = blockIdx.x * 128;
    const int bm = blockIdx.y * 128;

    const __half* srcs[3] = {Ahi, Alo, B};
    const int rowb[3] = {bm, bm, bn};

    float acc[4][8][4];
#pragma unroll
    for (int mi = 0; mi < 4; mi++)
#pragma unroll
        for (int ni = 0; ni < 8; ni++)
#pragma unroll
            for (int r = 0; r < 4; r++) acc[mi][ni][r] = 0.f;

    const int NI = K / TK;

    gemm_load_stage(sbase, srcs, rowb, 0, K, tid);
    CP_COMMIT();
    gemm_load_stage(sbase + STAGE, srcs, rowb, TK, K, tid);
    CP_COMMIT();

    int buf = 0;
    for (int i = 0; i < NI; i++) {
        if (i + 1 < NI) { CP_WAIT(1); } else { CP_WAIT(0); }
        __syncthreads();

        if (i + 2 < NI) {
            int nb = buf + 2; if (nb >= 3) nb -= 3;
            gemm_load_stage(sbase + nb * STAGE, srcs, rowb, (i + 2) * TK, K, tid);
            CP_COMMIT();
        }

        const uint32_t st = sbase + buf * STAGE;
        const uint32_t Ah = st, Al = st + TILE_B, Bh = st + 2 * TILE_B;
        const int ar = warpM * 64 + (lane & 15);
        const int br = warpN * 64 + (lane & 15);

#pragma unroll
        for (int ks = 0; ks < 2; ks++) {
            const int cc = ks * 2 + (lane >> 4);
            const uint32_t aoff = sw_off(ar, cc);
            const uint32_t boff = sw_off(br, cc);

            uint32_t ahf[4][4], alf[4][4];
#pragma unroll
            for (int mi = 0; mi < 4; mi++) {
                ldsm_x4(ahf[mi], Ah + aoff + mi * 1024);
                ldsm_x4(alf[mi], Al + aoff + mi * 1024);
            }
#pragma unroll
            for (int np = 0; np < 4; np++) {
                uint32_t bhf[4];
                ldsm_x4(bhf, Bh + boff + np * 1024);
#pragma unroll
                for (int mi = 0; mi < 4; mi++)
#pragma unroll
                    for (int o = 0; o < 2; o++) {
                        const int ni = np * 2 + o;
                        mma_f16(acc[mi][ni], ahf[mi], bhf[o], bhf[o + 2]);
                        mma_f16(acc[mi][ni], alf[mi], bhf[o], bhf[o + 2]);
                    }
            }
        }
        buf++; if (buf >= 3) buf = 0;
    }

#pragma unroll
    for (int mi = 0; mi < 4; mi++) {
        const int r0 = bm + warpM * 64 + mi * 16 + (lane >> 2);
#pragma unroll
        for (int ni = 0; ni < 8; ni++) {
            const int c0 = bn + warpN * 64 + ni * 8 + (lane & 3) * 2;
            const float b0 = bias[c0], b1 = bias[c0 + 1];
            float2 v0 = make_float2(acc[mi][ni][0] + b0, acc[mi][ni][1] + b1);
            float2 v1 = make_float2(acc[mi][ni][2] + b0, acc[mi][ni][3] + b1);
            *(float2*)(C + (size_t)r0 * N + c0) = v0;
            *(float2*)(C + (size_t)(r0 + 8) * N + c0) = v1;
        }
    }
}

// ---------------- fp16x2 HMMA flash attention --------------------------------
// Q split hi/lo; K, V single fp16.  S = Qh*K + Ql*K;  O = Ph*V + Pl*V.
#define KSTR 272                 // 128 fp16 = 256B + 16 pad
#define VSTR 144                 // 64 fp16 = 128B + 16 pad
#define KTILE (64*KSTR)          // 17408
#define VTILE (128*VSTR)         // 18432
#define ASTAGE (KTILE + VTILE)   // 35840
#define QSTR 272
#define QTILE (128*QSTR)         // 34816
#define ATTN_SMEM (2*QTILE + 2*ASTAGE)  // 141312

__device__ __forceinline__ void attn_load_kv(uint32_t st, int bh, int k0, int tid)
{
#pragma unroll
    for (int it = 0; it < 8; it++) {
        int idx = it * 256 + tid;          // 2048 chunks
        int sec = idx >> 10, rem = idx & 1023;
        if (sec == 0) {                    // K tile: 64 rows x 16 chunks
            int r = rem >> 4, c = rem & 15;
            uint32_t dst = st + r * KSTR + c * 16;
            const void* src = g_k + ((size_t)bh * SEQ + k0 + r) * DH + c * 8;
            CP_ASYNC16(dst, src);
        } else {                           // V tile: 128 rows x 8 chunks
            int r = rem >> 3, c = rem & 7;
            uint32_t dst = st + KTILE + r * VSTR + c * 16;
            const void* src = g_vt + ((size_t)bh * DH + r) * SEQ + k0 + c * 8;
            CP_ASYNC16(dst, src);
        }
    }
}

__global__ __launch_bounds__(256, 1)
void attn_hmma()
{
    extern __shared__ char sm[];
    const uint32_t sbase = smem_u32(sm);
    const uint32_t qb_smem = sbase;
    const uint32_t stage0 = sbase + 2 * QTILE;

    const int qb = 15 - blockIdx.x;
    const int h = blockIdx.y, b = blockIdx.z;
    const int bh = b * NH + h;
    const int q0 = qb * 128;
    const int tid = threadIdx.x;
    const int w = tid >> 5;
    const int lane = tid & 31;
    const float scale = 0.08838834764831845f;

#pragma unroll
    for (int it = 0; it < 16; it++) {
        int idx = it * 256 + tid;
        int sec = idx >> 11, rem = idx & 2047;
        int r = rem >> 4, c = rem & 15;
        uint32_t dst = qb_smem + sec * QTILE + r * QSTR + c * 16;
        const void* src = (sec ? g_qlo : g_qhi) + ((size_t)bh * SEQ + q0 + r) * DH + c * 8;
        CP_ASYNC16(dst, src);
    }
    CP_COMMIT();
    CP_WAIT(0);
    __syncthreads();

    uint32_t qh[8][4], ql[8][4];
    {
        const uint32_t arow = (w * 16 + (lane & 15)) * QSTR + (lane >> 4) * 16;
#pragma unroll
        for (int kt = 0; kt < 8; kt++) {
            ldsm_x4(qh[kt], qb_smem + arow + kt * 32);
            ldsm_x4(ql[kt], qb_smem + QTILE + arow + kt * 32);
        }
    }

    float oa[16][4];
#pragma unroll
    for (int dt = 0; dt < 16; dt++)
#pragma unroll
        for (int r = 0; r < 4; r++) oa[dt][r] = 0.f;
    float m0 = -1e30f, m1 = -1e30f, l0 = 0.f, l1 = 0.f;

    const int nch = 2 * qb + 2;

    attn_load_kv(stage0, bh, 0, tid);
    CP_COMMIT();

    for (int kb = 0; kb < nch; kb++) {
        if (kb + 1 < nch) {
            attn_load_kv(stage0 + ((kb + 1) & 1) * ASTAGE, bh, (kb + 1) * 64, tid);
            CP_COMMIT();
            CP_WAIT(1);
        } else {
            CP_WAIT(0);
        }
        __syncthreads();

        const uint32_t st = stage0 + (kb & 1) * ASTAGE;
        const int k0 = kb * 64;

        float e[8][4];
#pragma unroll
        for (int nt = 0; nt < 8; nt++)
#pragma unroll
            for (int r = 0; r < 4; r++) e[nt][r] = 0.f;

#pragma unroll
        for (int kt = 0; kt < 8; kt++) {
            const uint32_t ko = kt * 32 + (lane >> 4) * 16;
#pragma unroll
            for (int np = 0; np < 4; np++) {
                const uint32_t brow = (np * 16 + (lane & 15)) * KSTR + ko;
                uint32_t bhf[4];
                ldsm_x4(bhf, st + brow);
#pragma unroll
                for (int o = 0; o < 2; o++) {
                    const int nt = 2 * np + o;
                    mma_f16(e[nt], qh[kt], bhf[o], bhf[o + 2]);
                    mma_f16(e[nt], ql[kt], bhf[o], bhf[o + 2]);
                }
            }
        }

#pragma unroll
        for (int nt = 0; nt < 8; nt++)
#pragma unroll
            for (int r = 0; r < 4; r++) e[nt][r] *= scale;

        const int row0 = q0 + w * 16 + (lane >> 2);
        if (kb >= 2 * qb) {
#pragma unroll
            for (int nt = 0; nt < 8; nt++) {
                const int col = k0 + nt * 8 + (lane & 3) * 2;
                if (col     > row0)     e[nt][0] = -1e30f;
                if (col + 1 > row0)     e[nt][1] = -1e30f;
                if (col     > row0 + 8) e[nt][2] = -1e30f;
                if (col + 1 > row0 + 8) e[nt][3] = -1e30f;
            }
        }

        float rm0 = e[0][0], rm1 = e[0][2];
#pragma unroll
        for (int nt = 0; nt < 8; nt++) {
            rm0 = fmaxf(rm0, fmaxf(e[nt][0], e[nt][1]));
            rm1 = fmaxf(rm1, fmaxf(e[nt][2], e[nt][3]));
        }
        rm0 = fmaxf(rm0, __shfl_xor_sync(0xffffffffu, rm0, 1));
        rm0 = fmaxf(rm0, __shfl_xor_sync(0xffffffffu, rm0, 2));
        rm1 = fmaxf(rm1, __shfl_xor_sync(0xffffffffu, rm1, 1));
        rm1 = fmaxf(rm1, __shfl_xor_sync(0xffffffffu, rm1, 2));

        const float mn0 = fmaxf(m0, rm0), mn1 = fmaxf(m1, rm1);
        const float al0 = __expf(m0 - mn0), al1 = __expf(m1 - mn1);
        m0 = mn0; m1 = mn1;

        float s0 = 0.f, s1 = 0.f;
#pragma unroll
        for (int nt = 0; nt < 8; nt++) {
            e[nt][0] = __expf(e[nt][0] - mn0);
            e[nt][1] = __expf(e[nt][1] - mn0);
            e[nt][2] = __expf(e[nt][2] - mn1);
            e[nt][3] = __expf(e[nt][3] - mn1);
            s0 += e[nt][0] + e[nt][1];
            s1 += e[nt][2] + e[nt][3];
        }
        s0 += __shfl_xor_sync(0xffffffffu, s0, 1);
        s0 += __shfl_xor_sync(0xffffffffu, s0, 2);
        s1 += __shfl_xor_sync(0xffffffffu, s1, 1);
        s1 += __shfl_xor_sync(0xffffffffu, s1, 2);
        l0 = l0 * al0 + s0;
        l1 = l1 * al1 + s1;

#pragma unroll
        for (int dt = 0; dt < 16; dt++) {
            oa[dt][0] *= al0; oa[dt][1] *= al0;
            oa[dt][2] *= al1; oa[dt][3] *= al1;
        }

        const uint32_t vb = st + KTILE;
#pragma unroll
        for (int kt2 = 0; kt2 < 4; kt2++) {
            const int ta = 2 * kt2, tb = ta + 1;
            uint32_t ph[4], pl[4];
            pack_hilo(e[ta][0], e[ta][1], ph[0], pl[0]);
            pack_hilo(e[ta][2], e[ta][3], ph[1], pl[1]);
            pack_hilo(e[tb][0], e[tb][1], ph[2], pl[2]);
            pack_hilo(e[tb][2], e[tb][3], ph[3], pl[3]);

            const uint32_t ko = kt2 * 32 + (lane >> 4) * 16;
#pragma unroll
            for (int np = 0; np < 8; np++) {
                const uint32_t brow = (np * 16 + (lane & 15)) * VSTR + ko;
                uint32_t bhf[4];
                ldsm_x4(bhf, vb + brow);
#pragma unroll
                for (int o = 0; o < 2; o++) {
                    const int dt = 2 * np + o;
                    mma_f16(oa[dt], ph, bhf[o], bhf[o + 2]);
                    mma_f16(oa[dt], pl, bhf[o], bhf[o + 2]);
                }
            }
        }
        __syncthreads();
    }

    const float inv0 = 1.f / l0, inv1 = 1.f / l1;
    const size_t tokA = (size_t)b * SEQ + q0 + w * 16 + (lane >> 2);
    const size_t tokB = tokA + 8;
    const int colb = h * DH + (lane & 3) * 2;
    uint32_t* ahi = (uint32_t*)g_ahi;
    uint32_t* alo = (uint32_t*)g_alo;
#pragma unroll
    for (int dt = 0; dt < 16; dt++) {
        const int col = colb + dt * 8;
        uint32_t hi, lo;
        pack_hilo(oa[dt][0] * inv0, oa[dt][1] * inv0, hi, lo);
        ahi[(tokA * DM + col) >> 1] = hi;
        alo[(tokA * DM + col) >> 1] = lo;
        pack_hilo(oa[dt][2] * inv1, oa[dt][3] * inv1, hi, lo);
        ahi[(tokB * DM + col) >> 1] = hi;
        alo[(tokB * DM + col) >> 1] = lo;
    }
}

// ---------------- launch -----------------------------------------------------
extern "C" void kernel_launch(void* const* d_in, const int* in_sizes, int n_in,
                              void* d_out, int out_size)
{
    const float* x     = (const float*)d_in[0];
    const float* w_qkv = (const float*)d_in[1];
    const float* b_qkv = (const float*)d_in[2];
    const float* w_out = (const float*)d_in[3];
    const float* b_out = (const float*)d_in[4];
    const float* rc    = (const float*)d_in[5];
    const float* rs    = (const float*)d_in[6];
    float* out = (float*)d_out;

    float* p_qkv;
    __half *p_xhi, *p_xlo, *p_ahi, *p_alo, *p_wq, *p_wo;
    cudaGetSymbolAddress((void**)&p_qkv, g_qkv);
    cudaGetSymbolAddress((void**)&p_xhi, g_xhi);
    cudaGetSymbolAddress((void**)&p_xlo, g_xlo);
    cudaGetSymbolAddress((void**)&p_ahi, g_ahi);
    cudaGetSymbolAddress((void**)&p_alo, g_alo);
    cudaGetSymbolAddress((void**)&p_wq, g_wqkvT);
    cudaGetSymbolAddress((void**)&p_wo, g_woutT);

    cudaFuncSetAttribute(gemm_tc,
                         cudaFuncAttributeMaxDynamicSharedMemorySize, GEMM_SMEM);
    cudaFuncSetAttribute(attn_hmma,
                         cudaFuncAttributeMaxDynamicSharedMemorySize, ATTN_SMEM);

    // 1) split x -> fp16 hi/lo
    {
        int n4 = NTOK * DM / 4;
        split_a<<<(n4 + 255) / 256, 256>>>(x, p_xhi, p_xlo, n4);
    }
    // 2) transpose weights -> fp16
    transpose_w<<<dim3(QKVN / 32, DM / 32), dim3(32, 8)>>>(w_qkv, p_wq, DM, QKVN);
    transpose_w<<<dim3(DM / 32, DM / 32), dim3(32, 8)>>>(w_out, p_wo, DM, DM);
    // 3) qkv = x @ w_qkv + b  (fp16x2 HMMA)
    gemm_tc<<<dim3(QKVN / 128, NTOK / 128), 128, GEMM_SMEM>>>(
        p_xhi, p_xlo, p_wq, b_qkv, p_qkv, NTOK, QKVN, DM);
    // 4) RoPE -> fp16 Q hi/lo, K ; V transpose -> [bh,d,s]
    rope_split<<<(BATCH * NH * SEQ * RH) / 256, 256>>>(p_qkv, rc, rs);
    v_transpose<<<dim3(DH / 32, SEQ / 32, BH), dim3(32, 8)>>>(p_qkv);
    // 5) fp16x2 HMMA flash attention -> g_ahi/g_alo
    attn_hmma<<<dim3(SEQ / 128, NH, BATCH), 256, ATTN_SMEM>>>();
    // 6) out = att @ w_out + b  (fp16x2 HMMA)
    gemm_tc<<<dim3(DM / 128, NTOK / 128), 128, GEMM_SMEM>>>(
        p_ahi, p_alo, p_wo, b_out, out, NTOK, DM, DM);
}